// round 14
// baseline (speedup 1.0000x reference)
#include <cuda_runtime.h>
#include <cuda_fp16.h>
#include <mma.h>
#include <math.h>

using namespace nvcuda;

#define Bb 2
#define Cc 320
#define Nn 1024
#define NHh 8
#define DHh 40
#define Ll 2
#define EPS 1e-5f
#define EDGE_SCALE 0.17677669529663687f
#define ATT_SCALE  0.15811388300841897f

// fp32 state
__device__ float g_node[Bb * Nn * Cc];
__device__ float g_edge[Bb * Nn * Nn];
__device__ float g_s[Bb * Cc];
__device__ float g_wsum[Bb * Nn];
// fp16-resident dataflow
__device__ __half g_node_h[Bb * Nn * Cc];
__device__ __half g_qk2_h[Bb * Nn * 2 * Cc];
__device__ __half g_y_h[Bb * Nn * Cc];
__device__ __half g_qkv_h[Bb * Nn * 3 * Cc];
__device__ __half g_sattn[Bb * NHh * Nn * Nn];
__device__ __half g_nodeout_h[Bb * Nn * Cc];
// pre-converted weights
__device__ __half g_qkw_h[2 * Cc * Cc];
__device__ __half g_qkvw_h[Ll * 3 * Cc * Cc];
__device__ __half g_projw_h[Ll * Cc * Cc];

__device__ __forceinline__ void cpa16(unsigned dst, const void* src) {
    asm volatile("cp.async.cg.shared.global [%0], [%1], 16;\n" :: "r"(dst), "l"(src));
}
#define CPA_COMMIT() asm volatile("cp.async.commit_group;\n" ::: "memory")
#define CPA_WAIT2()  asm volatile("cp.async.wait_group 2;\n" ::: "memory")
#define CPA_WAIT1()  asm volatile("cp.async.wait_group 1;\n" ::: "memory")
#define CPA_WAIT0()  asm volatile("cp.async.wait_group 0;\n" ::: "memory")

#define N4_QK  (2 * Cc * Cc / 4)
#define N4_QKV (Ll * 3 * Cc * Cc / 4)
#define N4_PRJ (Ll * Cc * Cc / 4)

__global__ void w2h_all(const float* __restrict__ qkw, const float* __restrict__ qkvw,
                        const float* __restrict__ projw) {
    int i = blockIdx.x * 256 + threadIdx.x;
    const float* s;
    __half* d;
    int j = i;
    if (j < N4_QK) { s = qkw; d = g_qkw_h; }
    else if ((j -= N4_QK) < N4_QKV) { s = qkvw; d = g_qkvw_h; }
    else if ((j -= N4_QKV) < N4_PRJ) { s = projw; d = g_projw_h; }
    else return;
    float4 v = *(const float4*)&s[j * 4];
    __half2 h0 = __floats2half2_rn(v.x, v.y);
    __half2 h1 = __floats2half2_rn(v.z, v.w);
    uint2 u;
    u.x = *reinterpret_cast<unsigned*>(&h0);
    u.y = *reinterpret_cast<unsigned*>(&h1);
    *reinterpret_cast<uint2*>(&d[j * 4]) = u;
}

__global__ void transpose_in(const float* __restrict__ x) {
    __shared__ float tile[32][33];
    int b = blockIdx.z;
    int c0 = blockIdx.y * 32, n0 = blockIdx.x * 32;
    int tx = threadIdx.x, ty = threadIdx.y;
    tile[ty][tx] = x[(long)b * Cc * Nn + (long)(c0 + ty) * Nn + n0 + tx];
    __syncthreads();
    float v = tile[tx][ty];
    long o = ((long)b * Nn + n0 + ty) * Cc + c0 + tx;
    g_node[o] = v;
    g_node_h[o] = __float2half(v);
}

__global__ void transpose_out(float* __restrict__ out) {
    __shared__ float tile[32][33];
    int b = blockIdx.z;
    int c0 = blockIdx.y * 32, n0 = blockIdx.x * 32;
    int tx = threadIdx.x, ty = threadIdx.y;
    tile[ty][tx] = g_node[((long)b * Nn + n0 + ty) * Cc + c0 + tx];
    __syncthreads();
    out[(long)b * Cc * Nn + (long)(c0 + ty) * Nn + n0 + tx] = tile[tx][ty];
}

// FP16 WMMA NT GEMM, fp32 accum, cp.async 3-stage (K-tile 64). Block 128x64, 256 thr.
#define GSTG 27648
__global__ void gemm_hh(const __half* __restrict__ A, const __half* __restrict__ W,
                        const float* __restrict__ bias, void* __restrict__ Cout,
                        int K, int lda, int ldw, int ldc,
                        long sA, long sW, long sC, float alpha, int outHalf) {
    extern __shared__ char gsm[];
    int z = blockIdx.z;
    A += (long)z * sA; W += (long)z * sW;
    int bm = blockIdx.y * 128, bn = blockIdx.x * 64;
    int tid = threadIdx.x;
    int w = tid >> 5, wm = w >> 1, wn = w & 1;
    wmma::fragment<wmma::accumulator, 16, 16, 16, float> c[2][2];
    #pragma unroll
    for (int i = 0; i < 2; i++)
        #pragma unroll
        for (int j = 0; j < 2; j++) wmma::fill_fragment(c[i][j], 0.f);
    unsigned smbase = (unsigned)__cvta_generic_to_shared(gsm);
    auto loadStage = [&](int k0, int s) {
        unsigned base = smbase + s * GSTG;
        #pragma unroll
        for (int i = 0; i < 4; i++) {
            int idx = tid + i * 256, r = idx >> 3, c8 = (idx & 7) * 8;
            cpa16(base + r * 144 + c8 * 2, &A[(long)(bm + r) * lda + k0 + c8]);
        }
        #pragma unroll
        for (int i = 0; i < 2; i++) {
            int idx = tid + i * 256, r = idx >> 3, c8 = (idx & 7) * 8;
            cpa16(base + 18432 + r * 144 + c8 * 2, &W[(long)(bn + r) * ldw + k0 + c8]);
        }
        CPA_COMMIT();
    };
    int nIter = K >> 6;
    loadStage(0, 0);
    if (nIter > 1) loadStage(64, 1);
    for (int k = 0; k < nIter; k++) {
        if (k + 2 < nIter) { loadStage((k + 2) * 64, (k + 2) % 3); CPA_WAIT2(); }
        else if (k + 1 < nIter) CPA_WAIT1();
        else CPA_WAIT0();
        __syncthreads();
        __half (*As)[72] = (__half(*)[72])(gsm + (k % 3) * GSTG);
        __half (*Ws)[72] = (__half(*)[72])(gsm + (k % 3) * GSTG + 18432);
        #pragma unroll
        for (int kk = 0; kk < 4; kk++) {
            wmma::fragment<wmma::matrix_a, 16, 16, 16, __half, wmma::row_major> a[2];
            wmma::fragment<wmma::matrix_b, 16, 16, 16, __half, wmma::col_major> bf[2];
            #pragma unroll
            for (int i = 0; i < 2; i++)
                wmma::load_matrix_sync(a[i], &As[wm * 32 + i * 16][kk * 16], 72);
            #pragma unroll
            for (int j = 0; j < 2; j++)
                wmma::load_matrix_sync(bf[j], &Ws[wn * 32 + j * 16][kk * 16], 72);
            #pragma unroll
            for (int i = 0; i < 2; i++)
                #pragma unroll
                for (int j = 0; j < 2; j++) wmma::mma_sync(c[i][j], a[i], bf[j], c[i][j]);
        }
        __syncthreads();
    }
    float (*Cs)[68] = (float(*)[68])gsm;
    #pragma unroll
    for (int i = 0; i < 2; i++)
        #pragma unroll
        for (int j = 0; j < 2; j++) {
            #pragma unroll
            for (int e = 0; e < c[i][j].num_elements; e++) c[i][j].x[e] *= alpha;
            wmma::store_matrix_sync(&Cs[wm * 32 + i * 16][wn * 32 + j * 16],
                                    c[i][j], 68, wmma::mem_row_major);
        }
    __syncthreads();
    if (outHalf) {
        __half* Ch = (__half*)Cout + (long)z * sC;
        #pragma unroll
        for (int i = 0; i < 8; i++) {
            int idx = tid + i * 256, r = idx >> 4, c4 = (idx & 15) * 4;
            float4 v = *(float4*)&Cs[r][c4];
            if (bias) {
                float4 bb = *(const float4*)&bias[bn + c4];
                v.x += bb.x; v.y += bb.y; v.z += bb.z; v.w += bb.w;
            }
            __half2 h0 = __floats2half2_rn(v.x, v.y);
            __half2 h1 = __floats2half2_rn(v.z, v.w);
            uint2 u;
            u.x = *reinterpret_cast<unsigned*>(&h0);
            u.y = *reinterpret_cast<unsigned*>(&h1);
            *reinterpret_cast<uint2*>(&Ch[(long)(bm + r) * ldc + bn + c4]) = u;
        }
    } else {
        float* Cf = (float*)Cout + (long)z * sC;
        #pragma unroll
        for (int i = 0; i < 8; i++) {
            int idx = tid + i * 256, r = idx >> 4, c4 = (idx & 15) * 4;
            float4 v = *(float4*)&Cs[r][c4];
            if (bias) {
                float4 bb = *(const float4*)&bias[bn + c4];
                v.x += bb.x; v.y += bb.y; v.z += bb.z; v.w += bb.w;
            }
            *(float4*)&Cf[(long)(bm + r) * ldc + bn + c4] = v;
        }
    }
}

// 64x64-tile FP16 GEMM for proj (fp32 out + bias). 128 thr, cp.async 3-stage.
#define GSTG64 18432
__global__ void gemm64_proj(const __half* __restrict__ A, const __half* __restrict__ W,
                            const float* __restrict__ bias, float* __restrict__ C,
                            int K, int lda, int ldw, int ldc) {
    extern __shared__ char gsm[];
    int bm = blockIdx.y * 64, bn = blockIdx.x * 64;
    int tid = threadIdx.x;  // 128
    int w = tid >> 5, wm = w >> 1, wn = w & 1;
    wmma::fragment<wmma::accumulator, 16, 16, 16, float> c[2][2];
    #pragma unroll
    for (int i = 0; i < 2; i++)
        #pragma unroll
        for (int j = 0; j < 2; j++) wmma::fill_fragment(c[i][j], 0.f);
    unsigned smbase = (unsigned)__cvta_generic_to_shared(gsm);
    auto loadStage = [&](int k0, int s) {
        unsigned base = smbase + s * GSTG64;
        #pragma unroll
        for (int i = 0; i < 4; i++) {
            int idx = tid + i * 128, r = idx >> 3, c8 = (idx & 7) * 8;
            cpa16(base + r * 144 + c8 * 2, &A[(long)(bm + r) * lda + k0 + c8]);
        }
        #pragma unroll
        for (int i = 0; i < 4; i++) {
            int idx = tid + i * 128, r = idx >> 3, c8 = (idx & 7) * 8;
            cpa16(base + 9216 + r * 144 + c8 * 2, &W[(long)(bn + r) * ldw + k0 + c8]);
        }
        CPA_COMMIT();
    };
    int nIter = K >> 6;
    loadStage(0, 0);
    if (nIter > 1) loadStage(64, 1);
    for (int k = 0; k < nIter; k++) {
        if (k + 2 < nIter) { loadStage((k + 2) * 64, (k + 2) % 3); CPA_WAIT2(); }
        else if (k + 1 < nIter) CPA_WAIT1();
        else CPA_WAIT0();
        __syncthreads();
        __half (*As)[72] = (__half(*)[72])(gsm + (k % 3) * GSTG64);
        __half (*Ws)[72] = (__half(*)[72])(gsm + (k % 3) * GSTG64 + 9216);
        #pragma unroll
        for (int kk = 0; kk < 4; kk++) {
            wmma::fragment<wmma::matrix_a, 16, 16, 16, __half, wmma::row_major> a[2];
            wmma::fragment<wmma::matrix_b, 16, 16, 16, __half, wmma::col_major> bf[2];
            #pragma unroll
            for (int i = 0; i < 2; i++)
                wmma::load_matrix_sync(a[i], &As[wm * 32 + i * 16][kk * 16], 72);
            #pragma unroll
            for (int j = 0; j < 2; j++)
                wmma::load_matrix_sync(bf[j], &Ws[wn * 32 + j * 16][kk * 16], 72);
            #pragma unroll
            for (int i = 0; i < 2; i++)
                #pragma unroll
                for (int j = 0; j < 2; j++) wmma::mma_sync(c[i][j], a[i], bf[j], c[i][j]);
        }
        __syncthreads();
    }
    float (*Cs)[68] = (float(*)[68])gsm;
    #pragma unroll
    for (int i = 0; i < 2; i++)
        #pragma unroll
        for (int j = 0; j < 2; j++)
            wmma::store_matrix_sync(&Cs[wm * 32 + i * 16][wn * 32 + j * 16],
                                    c[i][j], 68, wmma::mem_row_major);
    __syncthreads();
    #pragma unroll
    for (int i = 0; i < 8; i++) {
        int idx = tid + i * 128, r = idx >> 4, c4 = (idx & 15) * 4;
        float4 v = *(float4*)&Cs[r][c4];
        float4 bb = *(const float4*)&bias[bn + c4];
        v.x += bb.x; v.y += bb.y; v.z += bb.z; v.w += bb.w;
        *(float4*)&C[(long)(bm + r) * ldc + bn + c4] = v;
    }
}

// fused: blocks [0,256): warp-per-row edge softmax; blocks [256,258): fcp
__global__ void edgesm_fcp(const float* __restrict__ da, const float* __restrict__ fw,
                           const float* __restrict__ fb) {
    __shared__ float t[64];
    if (blockIdx.x < 256) {
        int row = blockIdx.x * 8 + (threadIdx.x >> 5);
        int lane = threadIdx.x & 31;
        float* p = g_edge + (long)row * Nn;
        float4 r[8];
        float mx = -INFINITY;
        #pragma unroll
        for (int k = 0; k < 8; k++) {
            r[k] = *(float4*)&p[lane * 4 + k * 128];
            mx = fmaxf(mx, fmaxf(fmaxf(r[k].x, r[k].y), fmaxf(r[k].z, r[k].w)));
        }
        #pragma unroll
        for (int o = 16; o > 0; o >>= 1) mx = fmaxf(mx, __shfl_xor_sync(0xffffffffu, mx, o));
        float Z = 0.f;
        #pragma unroll
        for (int k = 0; k < 8; k++) {
            r[k].x = __expf(r[k].x - mx); r[k].y = __expf(r[k].y - mx);
            r[k].z = __expf(r[k].z - mx); r[k].w = __expf(r[k].w - mx);
            Z += r[k].x + r[k].y + r[k].z + r[k].w;
        }
        #pragma unroll
        for (int o = 16; o > 0; o >>= 1) Z += __shfl_xor_sync(0xffffffffu, Z, o);
        float inv = 1.f / Z;
        #pragma unroll
        for (int k = 0; k < 8; k++) {
            r[k].x *= inv; r[k].y *= inv; r[k].z *= inv; r[k].w *= inv;
            *(float4*)&p[lane * 4 + k * 128] = r[k];
        }
    } else {
        int b = blockIdx.x - 256;
        int tid = threadIdx.x;
        if (tid < 64) {
            float s = 0.f;
            #pragma unroll
            for (int a = 0; a < 16; a++) s += da[(long)b * 16 * 64 + a * 64 + tid];
            t[tid] = s;
        }
        __syncthreads();
        for (int c = tid; c < Cc; c += 256) {
            float s = 16.f * fb[c];
            #pragma unroll
            for (int e = 0; e < 64; e++) s += t[e] * fw[c * 64 + e];
            g_s[b * Cc + c] = s;
        }
    }
}

// warp-per-row LN1 -> gate -> LN2, writes y as fp16.
__global__ void norm_kernel(const float* __restrict__ g1, const float* __restrict__ b1,
                            const float* __restrict__ g2, const float* __restrict__ b2) {
    int bn = blockIdx.x * 8 + (threadIdx.x >> 5);
    int b = bn >> 10, n = bn & 1023;
    int lane = threadIdx.x & 31;
    const float* xp = g_node + (long)bn * Cc;
    float x[10];
    float s = 0.f;
    #pragma unroll
    for (int j = 0; j < 10; j++) { x[j] = xp[lane + j * 32]; s += x[j]; }
    #pragma unroll
    for (int o = 16; o > 0; o >>= 1) s += __shfl_xor_sync(0xffffffffu, s, o);
    float mean = s * (1.f / Cc);
    float v = 0.f;
    #pragma unroll
    for (int j = 0; j < 10; j++) { x[j] -= mean; v += x[j] * x[j]; }
    #pragma unroll
    for (int o = 16; o > 0; o >>= 1) v += __shfl_xor_sync(0xffffffffu, v, o);
    float rstd = rsqrtf(v * (1.f / Cc) + EPS);
    float diag = g_edge[(long)b * Nn * Nn + (long)n * Nn + n];
    const float* gsp = g_s + b * Cc;
    float y[10];
    float s2 = 0.f;
    #pragma unroll
    for (int j = 0; j < 10; j++) {
        int c = lane + j * 32;
        float nt = x[j] * rstd * g1[c] + b1[c];
        y[j] = diag * nt * gsp[c] + nt;
        s2 += y[j];
    }
    #pragma unroll
    for (int o = 16; o > 0; o >>= 1) s2 += __shfl_xor_sync(0xffffffffu, s2, o);
    float mean2 = s2 * (1.f / Cc);
    float v2 = 0.f;
    #pragma unroll
    for (int j = 0; j < 10; j++) { y[j] -= mean2; v2 += y[j] * y[j]; }
    #pragma unroll
    for (int o = 16; o > 0; o >>= 1) v2 += __shfl_xor_sync(0xffffffffu, v2, o);
    float rstd2 = rsqrtf(v2 * (1.f / Cc) + EPS);
    __half* yp = g_y_h + (long)bn * Cc;
    #pragma unroll
    for (int j = 0; j < 10; j++) {
        int c = lane + j * 32;
        yp[c] = __float2half(y[j] * rstd2 * g2[c] + b2[c]);
    }
}

// attn scores (fp16 WMMA): RAW QK^T*ATT_SCALE -> g_sattn. 128x128 tiles.
__global__ void attn_score_half(void) {
    __shared__ char smraw[34816];
    __half (*Qs)[48] = (__half(*)[48])smraw;
    __half (*Ks)[48] = (__half(*)[48])(smraw + 12288);
    float (*Cs)[68] = (float(*)[68])smraw;
    int bh = blockIdx.z;
    int b = bh >> 3, h = bh & 7;
    int n0 = blockIdx.y * 128, m0 = blockIdx.x * 128;
    const __half* Qb = g_qkv_h + (long)b * Nn * 960 + h * DHh;
    const __half* Kb = Qb + Cc;
    int tid = threadIdx.x;  // 256
    for (int idx = tid; idx < 1024; idx += 256) {
        Qs[idx >> 3][40 + (idx & 7)] = __float2half(0.f);
        Ks[idx >> 3][40 + (idx & 7)] = __float2half(0.f);
    }
    for (int idx = tid; idx < 640; idx += 256) {
        int r = idx / 5, c8 = (idx % 5) * 8;
        *(uint4*)&Qs[r][c8] = *(const uint4*)&Qb[(long)(n0 + r) * 960 + c8];
        *(uint4*)&Ks[r][c8] = *(const uint4*)&Kb[(long)(m0 + r) * 960 + c8];
    }
    __syncthreads();
    int w = tid >> 5, wr = w >> 1, wc = w & 1;
    wmma::fragment<wmma::accumulator, 16, 16, 16, float> c[2][4];
    #pragma unroll
    for (int i = 0; i < 2; i++)
        #pragma unroll
        for (int j = 0; j < 4; j++) wmma::fill_fragment(c[i][j], 0.f);
    #pragma unroll
    for (int kk = 0; kk < 3; kk++) {
        wmma::fragment<wmma::matrix_a, 16, 16, 16, __half, wmma::row_major> a[2];
        wmma::fragment<wmma::matrix_b, 16, 16, 16, __half, wmma::col_major> bf[4];
        #pragma unroll
        for (int i = 0; i < 2; i++)
            wmma::load_matrix_sync(a[i], &Qs[wr * 32 + i * 16][kk * 16], 48);
        #pragma unroll
        for (int j = 0; j < 4; j++)
            wmma::load_matrix_sync(bf[j], &Ks[wc * 64 + j * 16][kk * 16], 48);
        #pragma unroll
        for (int i = 0; i < 2; i++)
            #pragma unroll
            for (int j = 0; j < 4; j++) wmma::mma_sync(c[i][j], a[i], bf[j], c[i][j]);
    }
    #pragma unroll
    for (int i = 0; i < 2; i++)
        #pragma unroll
        for (int j = 0; j < 4; j++)
            #pragma unroll
            for (int e = 0; e < c[i][j].num_elements; e++) c[i][j].x[e] *= ATT_SCALE;
    __half* op = g_sattn + ((long)b * NHh + h) * Nn * Nn;
    #pragma unroll
    for (int half = 0; half < 2; half++) {
        __syncthreads();
        if (wc == half) {
            #pragma unroll
            for (int i = 0; i < 2; i++)
                #pragma unroll
                for (int j = 0; j < 4; j++)
                    wmma::store_matrix_sync(&Cs[wr * 32 + i * 16][j * 16], c[i][j], 68,
                                            wmma::mem_row_major);
        }
        __syncthreads();
        #pragma unroll
        for (int i2 = 0; i2 < 8; i2++) {
            int idx = tid + i2 * 256;
            int r = idx >> 4, c4 = (idx & 15) * 4;
            float4 s = *(float4*)&Cs[r][c4];
            *(__half2*)&op[(long)(n0 + r) * Nn + m0 + half * 64 + c4]     = __floats2half2_rn(s.x, s.y);
            *(__half2*)&op[(long)(n0 + r) * Nn + m0 + half * 64 + c4 + 2] = __floats2half2_rn(s.z, s.w);
        }
    }
}

__device__ __forceinline__ void mergeTriple(float& m, float& z, float& s,
                                            float mo, float zo, float so) {
    float nm = fmaxf(m, mo);
    float f1 = __expf(m - nm), f2 = __expf(mo - nm);
    z = z * f1 + zo * f2;
    s = s * f1 + so * f2;
    m = nm;
}

// warp-per-head softmax + edge_new + edge update + wsum (probs in-place, uint4 I/O)
__global__ void softmax_ednew(const float* __restrict__ exp_w, const float* __restrict__ exp_b,
                              const float* __restrict__ red_w, const float* __restrict__ red_b) {
    __shared__ float es[Nn];
    __shared__ float Ts[NHh][Nn];
    __shared__ float red3[24];
    int bn = blockIdx.x;
    int b = bn >> 10, n = bn & 1023;
    int tid = threadIdx.x;
    int w = tid >> 5, lane = tid & 31;
    __half* Ab = g_sattn + (((long)b * NHh + w) * Nn + n) * Nn;
    float* ep = g_edge + (long)b * Nn * Nn + (long)n * Nn;
    *(float4*)&es[tid * 4] = *(const float4*)&ep[tid * 4];
    __syncthreads();
    float ew = exp_w[w], eb = exp_b[w], rw = red_w[w];

    float4 r[8], e[8];
    #pragma unroll
    for (int k = 0; k < 4; k++) {  // 8 halves per uint4, cols lane*8 + k*256
        uint4 u = *(const uint4*)&Ab[lane * 8 + k * 256];
        float2 fa = __half22float2(*(__half2*)&u.x);
        float2 fb2 = __half22float2(*(__half2*)&u.y);
        float2 fc = __half22float2(*(__half2*)&u.z);
        float2 fd = __half22float2(*(__half2*)&u.w);
        float4 ev0 = *(float4*)&es[lane * 8 + k * 256];
        float4 ev1 = *(float4*)&es[lane * 8 + k * 256 + 4];
        r[2 * k].x     = fa.x + ev0.x * ew + eb;
        r[2 * k].y     = fa.y + ev0.y * ew + eb;
        r[2 * k].z     = fb2.x + ev0.z * ew + eb;
        r[2 * k].w     = fb2.y + ev0.w * ew + eb;
        r[2 * k + 1].x = fc.x + ev1.x * ew + eb;
        r[2 * k + 1].y = fc.y + ev1.y * ew + eb;
        r[2 * k + 1].z = fd.x + ev1.z * ew + eb;
        r[2 * k + 1].w = fd.y + ev1.w * ew + eb;
    }
    float M = -INFINITY;
    #pragma unroll
    for (int k = 0; k < 8; k++)
        M = fmaxf(M, fmaxf(fmaxf(r[k].x, r[k].y), fmaxf(r[k].z, r[k].w)));
    #pragma unroll
    for (int o = 16; o > 0; o >>= 1) M = fmaxf(M, __shfl_xor_sync(0xffffffffu, M, o));
    float Z = 0.f;
    #pragma unroll
    for (int k = 0; k < 8; k++) {
        e[k].x = __expf(r[k].x - M); e[k].y = __expf(r[k].y - M);
        e[k].z = __expf(r[k].z - M); e[k].w = __expf(r[k].w - M);
        Z += e[k].x + e[k].y + e[k].z + e[k].w;
    }
    #pragma unroll
    for (int o = 16; o > 0; o >>= 1) Z += __shfl_xor_sync(0xffffffffu, Z, o);
    float inv = 1.f / Z;
    #pragma unroll
    for (int k = 0; k < 4; k++) {
        float4 a0, a1;
        a0.x = e[2 * k].x * inv;     a0.y = e[2 * k].y * inv;
        a0.z = e[2 * k].z * inv;     a0.w = e[2 * k].w * inv;
        a1.x = e[2 * k + 1].x * inv; a1.y = e[2 * k + 1].y * inv;
        a1.z = e[2 * k + 1].z * inv; a1.w = e[2 * k + 1].w * inv;
        uint4 u;
        __half2 p0 = __floats2half2_rn(a0.x, a0.y);
        __half2 p1 = __floats2half2_rn(a0.z, a0.w);
        __half2 p2 = __floats2half2_rn(a1.x, a1.y);
        __half2 p3 = __floats2half2_rn(a1.z, a1.w);
        u.x = *reinterpret_cast<unsigned*>(&p0);
        u.y = *reinterpret_cast<unsigned*>(&p1);
        u.z = *reinterpret_cast<unsigned*>(&p2);
        u.w = *reinterpret_cast<unsigned*>(&p3);
        *(uint4*)&Ab[lane * 8 + k * 256] = u;
        float4 t0, t1;
        t0.x = rw * (a0.x + r[2 * k].x); t0.y = rw * (a0.y + r[2 * k].y);
        t0.z = rw * (a0.z + r[2 * k].z); t0.w = rw * (a0.w + r[2 * k].w);
        t1.x = rw * (a1.x + r[2 * k + 1].x); t1.y = rw * (a1.y + r[2 * k + 1].y);
        t1.z = rw * (a1.z + r[2 * k + 1].z); t1.w = rw * (a1.w + r[2 * k + 1].w);
        *(float4*)&Ts[w][lane * 8 + k * 256]     = t0;
        *(float4*)&Ts[w][lane * 8 + k * 256 + 4] = t1;
    }
    __syncthreads();

    float rb = red_b[0];
    float4 en = {rb, rb, rb, rb};
    #pragma unroll
    for (int h = 0; h < NHh; h++) {
        float4 t = *(float4*)&Ts[h][tid * 4];
        en.x += t.x; en.y += t.y; en.z += t.z; en.w += t.w;
    }
    float4 ec = *(float4*)&es[tid * 4];
    ec.x += en.x; ec.y += en.y; ec.z += en.z; ec.w += en.w;
    *(float4*)&ep[tid * 4] = ec;
    float m2 = fmaxf(fmaxf(en.x, en.y), fmaxf(en.z, en.w));
    float f0 = __expf(en.x - m2), f1 = __expf(en.y - m2),
          f2 = __expf(en.z - m2), f3 = __expf(en.w - m2);
    float z2 = f0 + f1 + f2 + f3;
    float s2 = f0 * en.x + f1 * en.y + f2 * en.z + f3 * en.w;
    #pragma unroll
    for (int o = 16; o > 0; o >>= 1)
        mergeTriple(m2, z2, s2,
                    __shfl_xor_sync(0xffffffffu, m2, o),
                    __shfl_xor_sync(0xffffffffu, z2, o),
                    __shfl_xor_sync(0xffffffffu, s2, o));
    if (lane == 0) { red3[w * 3] = m2; red3[w * 3 + 1] = z2; red3[w * 3 + 2] = s2; }
    __syncthreads();
    if (tid < 32) {
        float mm = (lane < 8) ? red3[lane * 3]     : -INFINITY;
        float zz = (lane < 8) ? red3[lane * 3 + 1] : 0.f;
        float ss = (lane < 8) ? red3[lane * 3 + 2] : 0.f;
        #pragma unroll
        for (int o = 4; o > 0; o >>= 1)
            mergeTriple(mm, zz, ss,
                        __shfl_xor_sync(0xffffffffu, mm, o),
                        __shfl_xor_sync(0xffffffffu, zz, o),
                        __shfl_xor_sync(0xffffffffu, ss, o));
        if (lane == 0) g_wsum[bn] = ss / zz;
    }
}

// AV (fp16 WMMA): 64-row n-tiles, 128 thr, cp.async 3-stage (P 64x64 + V 64x40).
#define ASTG64 15360
__global__ void av_half(void) {
    extern __shared__ char avsm[];
    int bh = blockIdx.y;
    int b = bh >> 3, h = bh & 7;
    int n0 = blockIdx.x * 64;
    int tid = threadIdx.x;  // 128
    int w = tid >> 5;       // 4 warps x 16 rows
    const __half* Pb = g_sattn + (((long)b * NHh + h) * Nn + n0) * Nn;
    const __half* Vb = g_qkv_h + (long)b * Nn * 960 + 640 + h * DHh;
    unsigned smbase = (unsigned)__cvta_generic_to_shared(avsm);
    for (int s = 0; s < 3; s++) {
        __half* vp = (__half*)(avsm + s * ASTG64 + 9216);
        for (int idx = tid; idx < 512; idx += 128) vp[(idx >> 3) * 48 + 40 + (idx & 7)] = __float2half(0.f);
    }
    wmma::fragment<wmma::accumulator, 16, 16, 16, float> c[3];
    #pragma unroll
    for (int j = 0; j < 3; j++) wmma::fill_fragment(c[j], 0.f);
    auto loadStage = [&](int m0, int s) {
        unsigned base = smbase + s * ASTG64;
        #pragma unroll
        for (int i = 0; i < 4; i++) {
            int idx = tid + i * 128, r = idx >> 3, c8 = (idx & 7) * 8;
            cpa16(base + r * 144 + c8 * 2, &Pb[(long)r * Nn + m0 + c8]);
        }
        #pragma unroll
        for (int i = 0; i < 3; i++) {
            int idx = tid + i * 128;
            if (idx < 320) {
                int r = idx / 5, c8 = (idx % 5) * 8;
                cpa16(base + 9216 + r * 96 + c8 * 2, &Vb[(long)(m0 + r) * 960 + c8]);
            }
        }
        CPA_COMMIT();
    };
    loadStage(0, 0);
    loadStage(64, 1);
    for (int k = 0; k < 16; k++) {
        if (k + 2 < 16) { loadStage((k + 2) * 64, (k + 2) % 3); CPA_WAIT2(); }
        else if (k + 1 < 16) CPA_WAIT1();
        else CPA_WAIT0();
        __syncthreads();
        __half (*Ps)[72] = (__half(*)[72])(avsm + (k % 3) * ASTG64);
        __half (*Vs)[48] = (__half(*)[48])(avsm + (k % 3) * ASTG64 + 9216);
        #pragma unroll
        for (int kk = 0; kk < 4; kk++) {
            wmma::fragment<wmma::matrix_a, 16, 16, 16, __half, wmma::row_major> a;
            wmma::load_matrix_sync(a, &Ps[w * 16][kk * 16], 72);
            #pragma unroll
            for (int j = 0; j < 3; j++) {
                wmma::fragment<wmma::matrix_b, 16, 16, 16, __half, wmma::row_major> bf;
                wmma::load_matrix_sync(bf, &Vs[kk * 16][j * 16], 48);
                wmma::mma_sync(c[j], a, bf, c[j]);
            }
        }
        __syncthreads();
    }
    float (*Cs)[48] = (float(*)[48])avsm;
    #pragma unroll
    for (int j = 0; j < 3; j++)
        wmma::store_matrix_sync(&Cs[w * 16][j * 16], c[j], 48, wmma::mem_row_major);
    __syncthreads();
    const float* wsp = g_wsum + b * Nn + n0;
    __half* op = g_nodeout_h + ((long)b * Nn + n0) * Cc + h * DHh;
    for (int idx = tid; idx < 640; idx += 128) {
        int r = idx / 10, c4 = (idx % 10) * 4;
        float wv = wsp[r];
        float4 v = *(float4*)&Cs[r][c4];
        __half2 h0 = __floats2half2_rn(v.x + wv, v.y + wv);
        __half2 h1 = __floats2half2_rn(v.z + wv, v.w + wv);
        uint2 u;
        u.x = *reinterpret_cast<unsigned*>(&h0);
        u.y = *reinterpret_cast<unsigned*>(&h1);
        *reinterpret_cast<uint2*>(&op[(long)r * Cc + c4]) = u;
    }
}

static void* symv(const void* s) {
    void* p = nullptr;
    cudaGetSymbolAddress(&p, s);
    return p;
}

extern "C" void kernel_launch(void* const* d_in, const int* in_sizes, int n_in,
                              void* d_out, int out_size) {
    const float* x        = (const float*)d_in[0];
    const float* da_prior = (const float*)d_in[1];
    const float* qk_w     = (const float*)d_in[2];
    const float* fcp_w    = (const float*)d_in[3];
    const float* fcp_b    = (const float*)d_in[4];
    const float* ln1_g    = (const float*)d_in[5];
    const float* ln1_b    = (const float*)d_in[6];
    const float* gln_g    = (const float*)d_in[7];
    const float* gln_b    = (const float*)d_in[8];
    const float* qkv_w    = (const float*)d_in[9];
    const float* qkv_b    = (const float*)d_in[10];
    const float* proj_w   = (const float*)d_in[11];
    const float* proj_b   = (const float*)d_in[12];
    const float* exp_w    = (const float*)d_in[13];
    const float* exp_b    = (const float*)d_in[14];
    const float* red_w    = (const float*)d_in[15];
    const float* red_b    = (const float*)d_in[16];
    float* out = (float*)d_out;

    float*  p_node   = (float*)symv(g_node);
    float*  p_edge   = (float*)symv(g_edge);
    __half* p_node_h = (__half*)symv(g_node_h);
    __half* p_qk2_h  = (__half*)symv(g_qk2_h);
    __half* p_y_h    = (__half*)symv(g_y_h);
    __half* p_qkv_h  = (__half*)symv(g_qkv_h);
    __half* p_no_h   = (__half*)symv(g_nodeout_h);
    __half* p_qkw_h  = (__half*)symv(g_qkw_h);
    __half* p_qkvw_h = (__half*)symv(g_qkvw_h);
    __half* p_projw_h= (__half*)symv(g_projw_h);

    cudaFuncSetAttribute(gemm_hh, cudaFuncAttributeMaxDynamicSharedMemorySize, 3 * GSTG);
    cudaFuncSetAttribute(gemm64_proj, cudaFuncAttributeMaxDynamicSharedMemorySize, 3 * GSTG64);
    cudaFuncSetAttribute(av_half, cudaFuncAttributeMaxDynamicSharedMemorySize, 3 * ASTG64);

    w2h_all<<<(N4_QK + N4_QKV + N4_PRJ + 255) / 256, 256>>>(qk_w, qkv_w, proj_w);
    transpose_in<<<dim3(32, 10, Bb), dim3(32, 32)>>>(x);
    gemm_hh<<<dim3(10, 16, 1), 256, 3 * GSTG>>>(p_node_h, p_qkw_h, nullptr, p_qk2_h,
                                                Cc, Cc, Cc, 2 * Cc, 0, 0, 0, 1.f, 1);
    gemm_hh<<<dim3(16, 8, Bb), 256, 3 * GSTG>>>(p_qk2_h, p_qk2_h + Cc, nullptr, p_edge,
                                                Cc, 2 * Cc, 2 * Cc, Nn,
                                                (long)Nn * 2 * Cc, (long)Nn * 2 * Cc,
                                                (long)Nn * Nn, EDGE_SCALE, 0);
    edgesm_fcp<<<258, 256>>>(da_prior, fcp_w, fcp_b);

    for (int l = 0; l < Ll; l++) {
        norm_kernel<<<Bb * Nn / 8, 256>>>(ln1_g + l * Cc, ln1_b + l * Cc,
                                          gln_g + l * Cc, gln_b + l * Cc);
        gemm_hh<<<dim3(15, 16, 1), 256, 3 * GSTG>>>(p_y_h, p_qkvw_h + (long)l * 3 * Cc * Cc,
                                                    qkv_b + l * 3 * Cc, p_qkv_h,
                                                    Cc, Cc, Cc, 3 * Cc, 0, 0, 0, 1.f, 1);
        attn_score_half<<<dim3(8, 8, Bb * NHh), 256>>>();
        softmax_ednew<<<Bb * Nn, 256>>>(exp_w + l * NHh, exp_b + l * NHh,
                                        red_w + l * NHh, red_b + l);
        av_half<<<dim3(16, Bb * NHh), 128, 3 * ASTG64>>>();
        gemm64_proj<<<dim3(5, 32), 128, 3 * GSTG64>>>(p_no_h, p_projw_h + (long)l * Cc * Cc,
                                                      proj_b + l * Cc, p_node,
                                                      Cc, Cc, Cc, Cc);
    }
    transpose_out<<<dim3(32, 10, Bb), dim3(32, 32)>>>(out);
}

// round 15
// speedup vs baseline: 1.0175x; 1.0175x over previous
#include <cuda_runtime.h>
#include <cuda_fp16.h>
#include <mma.h>
#include <math.h>

using namespace nvcuda;

#define Bb 2
#define Cc 320
#define Nn 1024
#define NHh 8
#define DHh 40
#define Ll 2
#define EPS 1e-5f
#define EDGE_SCALE 0.17677669529663687f
#define ATT_SCALE  0.15811388300841897f

// fp32 state
__device__ float g_node[Bb * Nn * Cc];
__device__ float g_edge[Bb * Nn * Nn];
__device__ float g_s[Bb * Cc];
__device__ float g_wsum[Bb * Nn];
// fp16-resident dataflow
__device__ __half g_node_h[Bb * Nn * Cc];
__device__ __half g_qk2_h[Bb * Nn * 2 * Cc];
__device__ __half g_y_h[Bb * Nn * Cc];
__device__ __half g_qkv_h[Bb * Nn * 3 * Cc];
__device__ __half g_sattn[Bb * NHh * Nn * Nn];
__device__ __half g_nodeout_h[Bb * Nn * Cc];
// pre-converted weights
__device__ __half g_qkw_h[2 * Cc * Cc];
__device__ __half g_qkvw_h[Ll * 3 * Cc * Cc];
__device__ __half g_projw_h[Ll * Cc * Cc];

__device__ __forceinline__ void cpa16(unsigned dst, const void* src) {
    asm volatile("cp.async.cg.shared.global [%0], [%1], 16;\n" :: "r"(dst), "l"(src));
}
#define CPA_COMMIT() asm volatile("cp.async.commit_group;\n" ::: "memory")
#define CPA_WAIT1()  asm volatile("cp.async.wait_group 1;\n" ::: "memory")
#define CPA_WAIT0()  asm volatile("cp.async.wait_group 0;\n" ::: "memory")

#define N4_QK  (2 * Cc * Cc / 4)
#define N4_QKV (Ll * 3 * Cc * Cc / 4)
#define N4_PRJ (Ll * Cc * Cc / 4)

__global__ void w2h_all(const float* __restrict__ qkw, const float* __restrict__ qkvw,
                        const float* __restrict__ projw) {
    int i = blockIdx.x * 256 + threadIdx.x;
    const float* s;
    __half* d;
    int j = i;
    if (j < N4_QK) { s = qkw; d = g_qkw_h; }
    else if ((j -= N4_QK) < N4_QKV) { s = qkvw; d = g_qkvw_h; }
    else if ((j -= N4_QKV) < N4_PRJ) { s = projw; d = g_projw_h; }
    else return;
    float4 v = *(const float4*)&s[j * 4];
    __half2 h0 = __floats2half2_rn(v.x, v.y);
    __half2 h1 = __floats2half2_rn(v.z, v.w);
    uint2 u;
    u.x = *reinterpret_cast<unsigned*>(&h0);
    u.y = *reinterpret_cast<unsigned*>(&h1);
    *reinterpret_cast<uint2*>(&d[j * 4]) = u;
}

// 256-thread transpose: 32x32 tile, 4 rows/thread
__global__ void transpose_in(const float* __restrict__ x) {
    __shared__ float tile[32][33];
    int b = blockIdx.z;
    int c0 = blockIdx.y * 32, n0 = blockIdx.x * 32;
    int tx = threadIdx.x & 31, ty0 = (threadIdx.x >> 5) * 4;
    #pragma unroll
    for (int j = 0; j < 4; j++)
        tile[ty0 + j][tx] = x[(long)b * Cc * Nn + (long)(c0 + ty0 + j) * Nn + n0 + tx];
    __syncthreads();
    #pragma unroll
    for (int j = 0; j < 4; j++) {
        float v = tile[tx][ty0 + j];
        long o = ((long)b * Nn + n0 + ty0 + j) * Cc + c0 + tx;
        g_node[o] = v;
        g_node_h[o] = __float2half(v);
    }
}

__global__ void transpose_out(float* __restrict__ out) {
    __shared__ float tile[32][33];
    int b = blockIdx.z;
    int c0 = blockIdx.y * 32, n0 = blockIdx.x * 32;
    int tx = threadIdx.x & 31, ty0 = (threadIdx.x >> 5) * 4;
    #pragma unroll
    for (int j = 0; j < 4; j++)
        tile[ty0 + j][tx] = g_node[((long)b * Nn + n0 + ty0 + j) * Cc + c0 + tx];
    __syncthreads();
    #pragma unroll
    for (int j = 0; j < 4; j++)
        out[(long)b * Cc * Nn + (long)(c0 + ty0 + j) * Nn + n0 + tx] = tile[tx][ty0 + j];
}

// FP16 WMMA NT GEMM, fp32 accum, cp.async 2-stage (K-tile 64). Block 128x64, 256 thr.
#define GSTG 27648
__global__ void gemm_hh(const __half* __restrict__ A, const __half* __restrict__ W,
                        const float* __restrict__ bias, void* __restrict__ Cout,
                        int K, int lda, int ldw, int ldc,
                        long sA, long sW, long sC, float alpha, int outHalf) {
    extern __shared__ char gsm[];
    int z = blockIdx.z;
    A += (long)z * sA; W += (long)z * sW;
    int bm = blockIdx.y * 128, bn = blockIdx.x * 64;
    int tid = threadIdx.x;
    int w = tid >> 5, wm = w >> 1, wn = w & 1;
    wmma::fragment<wmma::accumulator, 16, 16, 16, float> c[2][2];
    #pragma unroll
    for (int i = 0; i < 2; i++)
        #pragma unroll
        for (int j = 0; j < 2; j++) wmma::fill_fragment(c[i][j], 0.f);
    unsigned smbase = (unsigned)__cvta_generic_to_shared(gsm);
    auto loadStage = [&](int k0, int s) {
        unsigned base = smbase + s * GSTG;
        #pragma unroll
        for (int i = 0; i < 4; i++) {
            int idx = tid + i * 256, r = idx >> 3, c8 = (idx & 7) * 8;
            cpa16(base + r * 144 + c8 * 2, &A[(long)(bm + r) * lda + k0 + c8]);
        }
        #pragma unroll
        for (int i = 0; i < 2; i++) {
            int idx = tid + i * 256, r = idx >> 3, c8 = (idx & 7) * 8;
            cpa16(base + 18432 + r * 144 + c8 * 2, &W[(long)(bn + r) * ldw + k0 + c8]);
        }
        CPA_COMMIT();
    };
    int nIter = K >> 6;
    loadStage(0, 0);
    for (int k = 0; k < nIter; k++) {
        if (k + 1 < nIter) { loadStage((k + 1) * 64, (k + 1) & 1); CPA_WAIT1(); }
        else CPA_WAIT0();
        __syncthreads();
        __half (*As)[72] = (__half(*)[72])(gsm + (k & 1) * GSTG);
        __half (*Ws)[72] = (__half(*)[72])(gsm + (k & 1) * GSTG + 18432);
        #pragma unroll
        for (int kk = 0; kk < 4; kk++) {
            wmma::fragment<wmma::matrix_a, 16, 16, 16, __half, wmma::row_major> a[2];
            wmma::fragment<wmma::matrix_b, 16, 16, 16, __half, wmma::col_major> bf[2];
            #pragma unroll
            for (int i = 0; i < 2; i++)
                wmma::load_matrix_sync(a[i], &As[wm * 32 + i * 16][kk * 16], 72);
            #pragma unroll
            for (int j = 0; j < 2; j++)
                wmma::load_matrix_sync(bf[j], &Ws[wn * 32 + j * 16][kk * 16], 72);
            #pragma unroll
            for (int i = 0; i < 2; i++)
                #pragma unroll
                for (int j = 0; j < 2; j++) wmma::mma_sync(c[i][j], a[i], bf[j], c[i][j]);
        }
        __syncthreads();
    }
    float (*Cs)[68] = (float(*)[68])gsm;
    #pragma unroll
    for (int i = 0; i < 2; i++)
        #pragma unroll
        for (int j = 0; j < 2; j++) {
            #pragma unroll
            for (int e = 0; e < c[i][j].num_elements; e++) c[i][j].x[e] *= alpha;
            wmma::store_matrix_sync(&Cs[wm * 32 + i * 16][wn * 32 + j * 16],
                                    c[i][j], 68, wmma::mem_row_major);
        }
    __syncthreads();
    if (outHalf) {
        __half* Ch = (__half*)Cout + (long)z * sC;
        #pragma unroll
        for (int i = 0; i < 8; i++) {
            int idx = tid + i * 256, r = idx >> 4, c4 = (idx & 15) * 4;
            float4 v = *(float4*)&Cs[r][c4];
            if (bias) {
                float4 bb = *(const float4*)&bias[bn + c4];
                v.x += bb.x; v.y += bb.y; v.z += bb.z; v.w += bb.w;
            }
            __half2 h0 = __floats2half2_rn(v.x, v.y);
            __half2 h1 = __floats2half2_rn(v.z, v.w);
            uint2 u;
            u.x = *reinterpret_cast<unsigned*>(&h0);
            u.y = *reinterpret_cast<unsigned*>(&h1);
            *reinterpret_cast<uint2*>(&Ch[(long)(bm + r) * ldc + bn + c4]) = u;
        }
    } else {
        float* Cf = (float*)Cout + (long)z * sC;
        #pragma unroll
        for (int i = 0; i < 8; i++) {
            int idx = tid + i * 256, r = idx >> 4, c4 = (idx & 15) * 4;
            float4 v = *(float4*)&Cs[r][c4];
            if (bias) {
                float4 bb = *(const float4*)&bias[bn + c4];
                v.x += bb.x; v.y += bb.y; v.z += bb.z; v.w += bb.w;
            }
            *(float4*)&Cf[(long)(bm + r) * ldc + bn + c4] = v;
        }
    }
}

// 64x64-tile FP16 GEMM for proj (fp32 out + bias). 128 thr, cp.async 2-stage.
#define GSTG64 18432
__global__ void gemm64_proj(const __half* __restrict__ A, const __half* __restrict__ W,
                            const float* __restrict__ bias, float* __restrict__ C,
                            int K, int lda, int ldw, int ldc) {
    extern __shared__ char gsm[];
    int bm = blockIdx.y * 64, bn = blockIdx.x * 64;
    int tid = threadIdx.x;  // 128
    int w = tid >> 5, wm = w >> 1, wn = w & 1;
    wmma::fragment<wmma::accumulator, 16, 16, 16, float> c[2][2];
    #pragma unroll
    for (int i = 0; i < 2; i++)
        #pragma unroll
        for (int j = 0; j < 2; j++) wmma::fill_fragment(c[i][j], 0.f);
    unsigned smbase = (unsigned)__cvta_generic_to_shared(gsm);
    auto loadStage = [&](int k0, int s) {
        unsigned base = smbase + s * GSTG64;
        #pragma unroll
        for (int i = 0; i < 4; i++) {
            int idx = tid + i * 128, r = idx >> 3, c8 = (idx & 7) * 8;
            cpa16(base + r * 144 + c8 * 2, &A[(long)(bm + r) * lda + k0 + c8]);
        }
        #pragma unroll
        for (int i = 0; i < 4; i++) {
            int idx = tid + i * 128, r = idx >> 3, c8 = (idx & 7) * 8;
            cpa16(base + 9216 + r * 144 + c8 * 2, &W[(long)(bn + r) * ldw + k0 + c8]);
        }
        CPA_COMMIT();
    };
    int nIter = K >> 6;
    loadStage(0, 0);
    for (int k = 0; k < nIter; k++) {
        if (k + 1 < nIter) { loadStage((k + 1) * 64, (k + 1) & 1); CPA_WAIT1(); }
        else CPA_WAIT0();
        __syncthreads();
        __half (*As)[72] = (__half(*)[72])(gsm + (k & 1) * GSTG64);
        __half (*Ws)[72] = (__half(*)[72])(gsm + (k & 1) * GSTG64 + 9216);
        #pragma unroll
        for (int kk = 0; kk < 4; kk++) {
            wmma::fragment<wmma::matrix_a, 16, 16, 16, __half, wmma::row_major> a[2];
            wmma::fragment<wmma::matrix_b, 16, 16, 16, __half, wmma::col_major> bf[2];
            #pragma unroll
            for (int i = 0; i < 2; i++)
                wmma::load_matrix_sync(a[i], &As[wm * 32 + i * 16][kk * 16], 72);
            #pragma unroll
            for (int j = 0; j < 2; j++)
                wmma::load_matrix_sync(bf[j], &Ws[wn * 32 + j * 16][kk * 16], 72);
            #pragma unroll
            for (int i = 0; i < 2; i++)
                #pragma unroll
                for (int j = 0; j < 2; j++) wmma::mma_sync(c[i][j], a[i], bf[j], c[i][j]);
        }
        __syncthreads();
    }
    float (*Cs)[68] = (float(*)[68])gsm;
    #pragma unroll
    for (int i = 0; i < 2; i++)
        #pragma unroll
        for (int j = 0; j < 2; j++)
            wmma::store_matrix_sync(&Cs[wm * 32 + i * 16][wn * 32 + j * 16],
                                    c[i][j], 68, wmma::mem_row_major);
    __syncthreads();
    #pragma unroll
    for (int i = 0; i < 8; i++) {
        int idx = tid + i * 128, r = idx >> 4, c4 = (idx & 15) * 4;
        float4 v = *(float4*)&Cs[r][c4];
        float4 bb = *(const float4*)&bias[bn + c4];
        v.x += bb.x; v.y += bb.y; v.z += bb.z; v.w += bb.w;
        *(float4*)&C[(long)(bm + r) * ldc + bn + c4] = v;
    }
}

// fused: blocks [0,256): warp-per-row edge softmax; blocks [256,258): fcp
__global__ void edgesm_fcp(const float* __restrict__ da, const float* __restrict__ fw,
                           const float* __restrict__ fb) {
    __shared__ float t[64];
    if (blockIdx.x < 256) {
        int row = blockIdx.x * 8 + (threadIdx.x >> 5);
        int lane = threadIdx.x & 31;
        float* p = g_edge + (long)row * Nn;
        float4 r[8];
        float mx = -INFINITY;
        #pragma unroll
        for (int k = 0; k < 8; k++) {
            r[k] = *(float4*)&p[lane * 4 + k * 128];
            mx = fmaxf(mx, fmaxf(fmaxf(r[k].x, r[k].y), fmaxf(r[k].z, r[k].w)));
        }
        #pragma unroll
        for (int o = 16; o > 0; o >>= 1) mx = fmaxf(mx, __shfl_xor_sync(0xffffffffu, mx, o));
        float Z = 0.f;
        #pragma unroll
        for (int k = 0; k < 8; k++) {
            r[k].x = __expf(r[k].x - mx); r[k].y = __expf(r[k].y - mx);
            r[k].z = __expf(r[k].z - mx); r[k].w = __expf(r[k].w - mx);
            Z += r[k].x + r[k].y + r[k].z + r[k].w;
        }
        #pragma unroll
        for (int o = 16; o > 0; o >>= 1) Z += __shfl_xor_sync(0xffffffffu, Z, o);
        float inv = 1.f / Z;
        #pragma unroll
        for (int k = 0; k < 8; k++) {
            r[k].x *= inv; r[k].y *= inv; r[k].z *= inv; r[k].w *= inv;
            *(float4*)&p[lane * 4 + k * 128] = r[k];
        }
    } else {
        int b = blockIdx.x - 256;
        int tid = threadIdx.x;
        if (tid < 64) {
            float s = 0.f;
            #pragma unroll
            for (int a = 0; a < 16; a++) s += da[(long)b * 16 * 64 + a * 64 + tid];
            t[tid] = s;
        }
        __syncthreads();
        for (int c = tid; c < Cc; c += 256) {
            float s = 16.f * fb[c];
            #pragma unroll
            for (int e = 0; e < 64; e++) s += t[e] * fw[c * 64 + e];
            g_s[b * Cc + c] = s;
        }
    }
}

// warp-per-row LN1 -> gate -> LN2, writes y as fp16.
__global__ void norm_kernel(const float* __restrict__ g1, const float* __restrict__ b1,
                            const float* __restrict__ g2, const float* __restrict__ b2) {
    int bn = blockIdx.x * 8 + (threadIdx.x >> 5);
    int b = bn >> 10, n = bn & 1023;
    int lane = threadIdx.x & 31;
    const float* xp = g_node + (long)bn * Cc;
    float x[10];
    float s = 0.f;
    #pragma unroll
    for (int j = 0; j < 10; j++) { x[j] = xp[lane + j * 32]; s += x[j]; }
    #pragma unroll
    for (int o = 16; o > 0; o >>= 1) s += __shfl_xor_sync(0xffffffffu, s, o);
    float mean = s * (1.f / Cc);
    float v = 0.f;
    #pragma unroll
    for (int j = 0; j < 10; j++) { x[j] -= mean; v += x[j] * x[j]; }
    #pragma unroll
    for (int o = 16; o > 0; o >>= 1) v += __shfl_xor_sync(0xffffffffu, v, o);
    float rstd = rsqrtf(v * (1.f / Cc) + EPS);
    float diag = g_edge[(long)b * Nn * Nn + (long)n * Nn + n];
    const float* gsp = g_s + b * Cc;
    float y[10];
    float s2 = 0.f;
    #pragma unroll
    for (int j = 0; j < 10; j++) {
        int c = lane + j * 32;
        float nt = x[j] * rstd * g1[c] + b1[c];
        y[j] = diag * nt * gsp[c] + nt;
        s2 += y[j];
    }
    #pragma unroll
    for (int o = 16; o > 0; o >>= 1) s2 += __shfl_xor_sync(0xffffffffu, s2, o);
    float mean2 = s2 * (1.f / Cc);
    float v2 = 0.f;
    #pragma unroll
    for (int j = 0; j < 10; j++) { y[j] -= mean2; v2 += y[j] * y[j]; }
    #pragma unroll
    for (int o = 16; o > 0; o >>= 1) v2 += __shfl_xor_sync(0xffffffffu, v2, o);
    float rstd2 = rsqrtf(v2 * (1.f / Cc) + EPS);
    __half* yp = g_y_h + (long)bn * Cc;
    #pragma unroll
    for (int j = 0; j < 10; j++) {
        int c = lane + j * 32;
        yp[c] = __float2half(y[j] * rstd2 * g2[c] + b2[c]);
    }
}

// attn scores (fp16 WMMA): RAW QK^T*ATT_SCALE -> g_sattn. 128x128 tiles.
__global__ void attn_score_half(void) {
    __shared__ char smraw[34816];
    __half (*Qs)[48] = (__half(*)[48])smraw;
    __half (*Ks)[48] = (__half(*)[48])(smraw + 12288);
    float (*Cs)[68] = (float(*)[68])smraw;
    int bh = blockIdx.z;
    int b = bh >> 3, h = bh & 7;
    int n0 = blockIdx.y * 128, m0 = blockIdx.x * 128;
    const __half* Qb = g_qkv_h + (long)b * Nn * 960 + h * DHh;
    const __half* Kb = Qb + Cc;
    int tid = threadIdx.x;  // 256
    for (int idx = tid; idx < 1024; idx += 256) {
        Qs[idx >> 3][40 + (idx & 7)] = __float2half(0.f);
        Ks[idx >> 3][40 + (idx & 7)] = __float2half(0.f);
    }
    for (int idx = tid; idx < 640; idx += 256) {
        int r = idx / 5, c8 = (idx % 5) * 8;
        *(uint4*)&Qs[r][c8] = *(const uint4*)&Qb[(long)(n0 + r) * 960 + c8];
        *(uint4*)&Ks[r][c8] = *(const uint4*)&Kb[(long)(m0 + r) * 960 + c8];
    }
    __syncthreads();
    int w = tid >> 5, wr = w >> 1, wc = w & 1;
    wmma::fragment<wmma::accumulator, 16, 16, 16, float> c[2][4];
    #pragma unroll
    for (int i = 0; i < 2; i++)
        #pragma unroll
        for (int j = 0; j < 4; j++) wmma::fill_fragment(c[i][j], 0.f);
    #pragma unroll
    for (int kk = 0; kk < 3; kk++) {
        wmma::fragment<wmma::matrix_a, 16, 16, 16, __half, wmma::row_major> a[2];
        wmma::fragment<wmma::matrix_b, 16, 16, 16, __half, wmma::col_major> bf[4];
        #pragma unroll
        for (int i = 0; i < 2; i++)
            wmma::load_matrix_sync(a[i], &Qs[wr * 32 + i * 16][kk * 16], 48);
        #pragma unroll
        for (int j = 0; j < 4; j++)
            wmma::load_matrix_sync(bf[j], &Ks[wc * 64 + j * 16][kk * 16], 48);
        #pragma unroll
        for (int i = 0; i < 2; i++)
            #pragma unroll
            for (int j = 0; j < 4; j++) wmma::mma_sync(c[i][j], a[i], bf[j], c[i][j]);
    }
    #pragma unroll
    for (int i = 0; i < 2; i++)
        #pragma unroll
        for (int j = 0; j < 4; j++)
            #pragma unroll
            for (int e = 0; e < c[i][j].num_elements; e++) c[i][j].x[e] *= ATT_SCALE;
    __half* op = g_sattn + ((long)b * NHh + h) * Nn * Nn;
    #pragma unroll
    for (int half = 0; half < 2; half++) {
        __syncthreads();
        if (wc == half) {
            #pragma unroll
            for (int i = 0; i < 2; i++)
                #pragma unroll
                for (int j = 0; j < 4; j++)
                    wmma::store_matrix_sync(&Cs[wr * 32 + i * 16][j * 16], c[i][j], 68,
                                            wmma::mem_row_major);
        }
        __syncthreads();
        #pragma unroll
        for (int i2 = 0; i2 < 8; i2++) {
            int idx = tid + i2 * 256;
            int r = idx >> 4, c4 = (idx & 15) * 4;
            float4 s = *(float4*)&Cs[r][c4];
            *(__half2*)&op[(long)(n0 + r) * Nn + m0 + half * 64 + c4]     = __floats2half2_rn(s.x, s.y);
            *(__half2*)&op[(long)(n0 + r) * Nn + m0 + half * 64 + c4 + 2] = __floats2half2_rn(s.z, s.w);
        }
    }
}

__device__ __forceinline__ void mergeTriple(float& m, float& z, float& s,
                                            float mo, float zo, float so) {
    float nm = fmaxf(m, mo);
    float f1 = __expf(m - nm), f2 = __expf(mo - nm);
    z = z * f1 + zo * f2;
    s = s * f1 + so * f2;
    m = nm;
}

// warp-per-head softmax + edge_new + edge update + wsum (probs in-place, uint4 I/O)
__global__ void softmax_ednew(const float* __restrict__ exp_w, const float* __restrict__ exp_b,
                              const float* __restrict__ red_w, const float* __restrict__ red_b) {
    __shared__ float es[Nn];
    __shared__ float Ts[NHh][Nn];
    __shared__ float red3[24];
    int bn = blockIdx.x;
    int b = bn >> 10, n = bn & 1023;
    int tid = threadIdx.x;
    int w = tid >> 5, lane = tid & 31;
    __half* Ab = g_sattn + (((long)b * NHh + w) * Nn + n) * Nn;
    float* ep = g_edge + (long)b * Nn * Nn + (long)n * Nn;
    *(float4*)&es[tid * 4] = *(const float4*)&ep[tid * 4];
    __syncthreads();
    float ew = exp_w[w], eb = exp_b[w], rw = red_w[w];

    float4 r[8], e[8];
    #pragma unroll
    for (int k = 0; k < 4; k++) {  // 8 halves per uint4, cols lane*8 + k*256
        uint4 u = *(const uint4*)&Ab[lane * 8 + k * 256];
        float2 fa = __half22float2(*(__half2*)&u.x);
        float2 fb2 = __half22float2(*(__half2*)&u.y);
        float2 fc = __half22float2(*(__half2*)&u.z);
        float2 fd = __half22float2(*(__half2*)&u.w);
        float4 ev0 = *(float4*)&es[lane * 8 + k * 256];
        float4 ev1 = *(float4*)&es[lane * 8 + k * 256 + 4];
        r[2 * k].x     = fa.x + ev0.x * ew + eb;
        r[2 * k].y     = fa.y + ev0.y * ew + eb;
        r[2 * k].z     = fb2.x + ev0.z * ew + eb;
        r[2 * k].w     = fb2.y + ev0.w * ew + eb;
        r[2 * k + 1].x = fc.x + ev1.x * ew + eb;
        r[2 * k + 1].y = fc.y + ev1.y * ew + eb;
        r[2 * k + 1].z = fd.x + ev1.z * ew + eb;
        r[2 * k + 1].w = fd.y + ev1.w * ew + eb;
    }
    float M = -INFINITY;
    #pragma unroll
    for (int k = 0; k < 8; k++)
        M = fmaxf(M, fmaxf(fmaxf(r[k].x, r[k].y), fmaxf(r[k].z, r[k].w)));
    #pragma unroll
    for (int o = 16; o > 0; o >>= 1) M = fmaxf(M, __shfl_xor_sync(0xffffffffu, M, o));
    float Z = 0.f;
    #pragma unroll
    for (int k = 0; k < 8; k++) {
        e[k].x = __expf(r[k].x - M); e[k].y = __expf(r[k].y - M);
        e[k].z = __expf(r[k].z - M); e[k].w = __expf(r[k].w - M);
        Z += e[k].x + e[k].y + e[k].z + e[k].w;
    }
    #pragma unroll
    for (int o = 16; o > 0; o >>= 1) Z += __shfl_xor_sync(0xffffffffu, Z, o);
    float inv = 1.f / Z;
    #pragma unroll
    for (int k = 0; k < 4; k++) {
        float4 a0, a1;
        a0.x = e[2 * k].x * inv;     a0.y = e[2 * k].y * inv;
        a0.z = e[2 * k].z * inv;     a0.w = e[2 * k].w * inv;
        a1.x = e[2 * k + 1].x * inv; a1.y = e[2 * k + 1].y * inv;
        a1.z = e[2 * k + 1].z * inv; a1.w = e[2 * k + 1].w * inv;
        uint4 u;
        __half2 p0 = __floats2half2_rn(a0.x, a0.y);
        __half2 p1 = __floats2half2_rn(a0.z, a0.w);
        __half2 p2 = __floats2half2_rn(a1.x, a1.y);
        __half2 p3 = __floats2half2_rn(a1.z, a1.w);
        u.x = *reinterpret_cast<unsigned*>(&p0);
        u.y = *reinterpret_cast<unsigned*>(&p1);
        u.z = *reinterpret_cast<unsigned*>(&p2);
        u.w = *reinterpret_cast<unsigned*>(&p3);
        *(uint4*)&Ab[lane * 8 + k * 256] = u;
        float4 t0, t1;
        t0.x = rw * (a0.x + r[2 * k].x); t0.y = rw * (a0.y + r[2 * k].y);
        t0.z = rw * (a0.z + r[2 * k].z); t0.w = rw * (a0.w + r[2 * k].w);
        t1.x = rw * (a1.x + r[2 * k + 1].x); t1.y = rw * (a1.y + r[2 * k + 1].y);
        t1.z = rw * (a1.z + r[2 * k + 1].z); t1.w = rw * (a1.w + r[2 * k + 1].w);
        *(float4*)&Ts[w][lane * 8 + k * 256]     = t0;
        *(float4*)&Ts[w][lane * 8 + k * 256 + 4] = t1;
    }
    __syncthreads();

    float rb = red_b[0];
    float4 en = {rb, rb, rb, rb};
    #pragma unroll
    for (int h = 0; h < NHh; h++) {
        float4 t = *(float4*)&Ts[h][tid * 4];
        en.x += t.x; en.y += t.y; en.z += t.z; en.w += t.w;
    }
    float4 ec = *(float4*)&es[tid * 4];
    ec.x += en.x; ec.y += en.y; ec.z += en.z; ec.w += en.w;
    *(float4*)&ep[tid * 4] = ec;
    float m2 = fmaxf(fmaxf(en.x, en.y), fmaxf(en.z, en.w));
    float f0 = __expf(en.x - m2), f1 = __expf(en.y - m2),
          f2 = __expf(en.z - m2), f3 = __expf(en.w - m2);
    float z2 = f0 + f1 + f2 + f3;
    float s2 = f0 * en.x + f1 * en.y + f2 * en.z + f3 * en.w;
    #pragma unroll
    for (int o = 16; o > 0; o >>= 1)
        mergeTriple(m2, z2, s2,
                    __shfl_xor_sync(0xffffffffu, m2, o),
                    __shfl_xor_sync(0xffffffffu, z2, o),
                    __shfl_xor_sync(0xffffffffu, s2, o));
    if (lane == 0) { red3[w * 3] = m2; red3[w * 3 + 1] = z2; red3[w * 3 + 2] = s2; }
    __syncthreads();
    if (tid < 32) {
        float mm = (lane < 8) ? red3[lane * 3]     : -INFINITY;
        float zz = (lane < 8) ? red3[lane * 3 + 1] : 0.f;
        float ss = (lane < 8) ? red3[lane * 3 + 2] : 0.f;
        #pragma unroll
        for (int o = 4; o > 0; o >>= 1)
            mergeTriple(mm, zz, ss,
                        __shfl_xor_sync(0xffffffffu, mm, o),
                        __shfl_xor_sync(0xffffffffu, zz, o),
                        __shfl_xor_sync(0xffffffffu, ss, o));
        if (lane == 0) g_wsum[bn] = ss / zz;
    }
}

// AV (fp16 WMMA): 64-row n-tiles, 128 thr, cp.async 2-stage (P 64x64 + V 64x40).
#define ASTG64 15360
__global__ void av_half(void) {
    extern __shared__ char avsm[];
    int bh = blockIdx.y;
    int b = bh >> 3, h = bh & 7;
    int n0 = blockIdx.x * 64;
    int tid = threadIdx.x;  // 128
    int w = tid >> 5;
    const __half* Pb = g_sattn + (((long)b * NHh + h) * Nn + n0) * Nn;
    const __half* Vb = g_qkv_h + (long)b * Nn * 960 + 640 + h * DHh;
    unsigned smbase = (unsigned)__cvta_generic_to_shared(avsm);
    for (int s = 0; s < 2; s++) {
        __half* vp = (__half*)(avsm + s * ASTG64 + 9216);
        for (int idx = tid; idx < 512; idx += 128) vp[(idx >> 3) * 48 + 40 + (idx & 7)] = __float2half(0.f);
    }
    wmma::fragment<wmma::accumulator, 16, 16, 16, float> c[3];
    #pragma unroll
    for (int j = 0; j < 3; j++) wmma::fill_fragment(c[j], 0.f);
    auto loadStage = [&](int m0, int s) {
        unsigned base = smbase + s * ASTG64;
        #pragma unroll
        for (int i = 0; i < 4; i++) {
            int idx = tid + i * 128, r = idx >> 3, c8 = (idx & 7) * 8;
            cpa16(base + r * 144 + c8 * 2, &Pb[(long)r * Nn + m0 + c8]);
        }
        #pragma unroll
        for (int i = 0; i < 3; i++) {
            int idx = tid + i * 128;
            if (idx < 320) {
                int r = idx / 5, c8 = (idx % 5) * 8;
                cpa16(base + 9216 + r * 96 + c8 * 2, &Vb[(long)(m0 + r) * 960 + c8]);
            }
        }
        CPA_COMMIT();
    };
    loadStage(0, 0);
    for (int k = 0; k < 16; k++) {
        if (k + 1 < 16) { loadStage((k + 1) * 64, (k + 1) & 1); CPA_WAIT1(); }
        else CPA_WAIT0();
        __syncthreads();
        __half (*Ps)[72] = (__half(*)[72])(avsm + (k & 1) * ASTG64);
        __half (*Vs)[48] = (__half(*)[48])(avsm + (k & 1) * ASTG64 + 9216);
        #pragma unroll
        for (int kk = 0; kk < 4; kk++) {
            wmma::fragment<wmma::matrix_a, 16, 16, 16, __half, wmma::row_major> a;
            wmma::load_matrix_sync(a, &Ps[w * 16][kk * 16], 72);
            #pragma unroll
            for (int j = 0; j < 3; j++) {
                wmma::fragment<wmma::matrix_b, 16, 16, 16, __half, wmma::row_major> bf;
                wmma::load_matrix_sync(bf, &Vs[kk * 16][j * 16], 48);
                wmma::mma_sync(c[j], a, bf, c[j]);
            }
        }
        __syncthreads();
    }
    float (*Cs)[48] = (float(*)[48])avsm;
    #pragma unroll
    for (int j = 0; j < 3; j++)
        wmma::store_matrix_sync(&Cs[w * 16][j * 16], c[j], 48, wmma::mem_row_major);
    __syncthreads();
    const float* wsp = g_wsum + b * Nn + n0;
    __half* op = g_nodeout_h + ((long)b * Nn + n0) * Cc + h * DHh;
    for (int idx = tid; idx < 640; idx += 128) {
        int r = idx / 10, c4 = (idx % 10) * 4;
        float wv = wsp[r];
        float4 v = *(float4*)&Cs[r][c4];
        __half2 h0 = __floats2half2_rn(v.x + wv, v.y + wv);
        __half2 h1 = __floats2half2_rn(v.z + wv, v.w + wv);
        uint2 u;
        u.x = *reinterpret_cast<unsigned*>(&h0);
        u.y = *reinterpret_cast<unsigned*>(&h1);
        *reinterpret_cast<uint2*>(&op[(long)r * Cc + c4]) = u;
    }
}

static void* symv(const void* s) {
    void* p = nullptr;
    cudaGetSymbolAddress(&p, s);
    return p;
}

extern "C" void kernel_launch(void* const* d_in, const int* in_sizes, int n_in,
                              void* d_out, int out_size) {
    const float* x        = (const float*)d_in[0];
    const float* da_prior = (const float*)d_in[1];
    const float* qk_w     = (const float*)d_in[2];
    const float* fcp_w    = (const float*)d_in[3];
    const float* fcp_b    = (const float*)d_in[4];
    const float* ln1_g    = (const float*)d_in[5];
    const float* ln1_b    = (const float*)d_in[6];
    const float* gln_g    = (const float*)d_in[7];
    const float* gln_b    = (const float*)d_in[8];
    const float* qkv_w    = (const float*)d_in[9];
    const float* qkv_b    = (const float*)d_in[10];
    const float* proj_w   = (const float*)d_in[11];
    const float* proj_b   = (const float*)d_in[12];
    const float* exp_w    = (const float*)d_in[13];
    const float* exp_b    = (const float*)d_in[14];
    const float* red_w    = (const float*)d_in[15];
    const float* red_b    = (const float*)d_in[16];
    float* out = (float*)d_out;

    float*  p_node   = (float*)symv(g_node);
    float*  p_edge   = (float*)symv(g_edge);
    __half* p_node_h = (__half*)symv(g_node_h);
    __half* p_qk2_h  = (__half*)symv(g_qk2_h);
    __half* p_y_h    = (__half*)symv(g_y_h);
    __half* p_qkv_h  = (__half*)symv(g_qkv_h);
    __half* p_no_h   = (__half*)symv(g_nodeout_h);
    __half* p_qkw_h  = (__half*)symv(g_qkw_h);
    __half* p_qkvw_h = (__half*)symv(g_qkvw_h);
    __half* p_projw_h= (__half*)symv(g_projw_h);

    cudaFuncSetAttribute(gemm_hh, cudaFuncAttributeMaxDynamicSharedMemorySize, 2 * GSTG);
    cudaFuncSetAttribute(gemm64_proj, cudaFuncAttributeMaxDynamicSharedMemorySize, 2 * GSTG64);
    cudaFuncSetAttribute(av_half, cudaFuncAttributeMaxDynamicSharedMemorySize, 2 * ASTG64);

    w2h_all<<<(N4_QK + N4_QKV + N4_PRJ + 255) / 256, 256>>>(qk_w, qkv_w, proj_w);
    transpose_in<<<dim3(32, 10, Bb), 256>>>(x);
    gemm_hh<<<dim3(10, 16, 1), 256, 2 * GSTG>>>(p_node_h, p_qkw_h, nullptr, p_qk2_h,
                                                Cc, Cc, Cc, 2 * Cc, 0, 0, 0, 1.f, 1);
    gemm_hh<<<dim3(16, 8, Bb), 256, 2 * GSTG>>>(p_qk2_h, p_qk2_h + Cc, nullptr, p_edge,
                                                Cc, 2 * Cc, 2 * Cc, Nn,
                                                (long)Nn * 2 * Cc, (long)Nn * 2 * Cc,
                                                (long)Nn * Nn, EDGE_SCALE, 0);
    edgesm_fcp<<<258, 256>>>(da_prior, fcp_w, fcp_b);

    for (int l = 0; l < Ll; l++) {
        norm_kernel<<<Bb * Nn / 8, 256>>>(ln1_g + l * Cc, ln1_b + l * Cc,
                                          gln_g + l * Cc, gln_b + l * Cc);
        gemm_hh<<<dim3(15, 16, 1), 256, 2 * GSTG>>>(p_y_h, p_qkvw_h + (long)l * 3 * Cc * Cc,
                                                    qkv_b + l * 3 * Cc, p_qkv_h,
                                                    Cc, Cc, Cc, 3 * Cc, 0, 0, 0, 1.f, 1);
        attn_score_half<<<dim3(8, 8, Bb * NHh), 256>>>();
        softmax_ednew<<<Bb * Nn, 256>>>(exp_w + l * NHh, exp_b + l * NHh,
                                        red_w + l * NHh, red_b + l);
        av_half<<<dim3(16, Bb * NHh), 128, 2 * ASTG64>>>();
        gemm64_proj<<<dim3(5, 32), 128, 2 * GSTG64>>>(p_no_h, p_projw_h + (long)l * Cc * Cc,
                                                      proj_b + l * Cc, p_node,
                                                      Cc, Cc, Cc, Cc);
    }
    transpose_out<<<dim3(32, 10, Bb), 256>>>(out);
}

// round 16
// speedup vs baseline: 1.0319x; 1.0142x over previous
#include <cuda_runtime.h>
#include <cuda_fp16.h>
#include <mma.h>
#include <math.h>

using namespace nvcuda;

#define Bb 2
#define Cc 320
#define Nn 1024
#define NHh 8
#define DHh 40
#define Ll 2
#define EPS 1e-5f
#define EDGE_SCALE 0.17677669529663687f
#define ATT_SCALE  0.15811388300841897f

// fp32 state
__device__ float g_node[Bb * Nn * Cc];
__device__ float g_edge[Bb * Nn * Nn];
__device__ float g_s[Bb * Cc];
__device__ float g_wsum[Bb * Nn];
// fp16-resident dataflow
__device__ __half g_node_h[Bb * Nn * Cc];
__device__ __half g_qk2_h[Bb * Nn * 2 * Cc];
__device__ __half g_y_h[Bb * Nn * Cc];
__device__ __half g_qkv_h[Bb * Nn * 3 * Cc];
__device__ __half g_sattn[Bb * NHh * Nn * Nn];
__device__ __half g_nodeout_h[Bb * Nn * Cc];
// pre-converted weights
__device__ __half g_qkw_h[2 * Cc * Cc];
__device__ __half g_qkvw_h[Ll * 3 * Cc * Cc];
__device__ __half g_projw_h[Ll * Cc * Cc];

__device__ __forceinline__ void cpa16(unsigned dst, const void* src) {
    asm volatile("cp.async.cg.shared.global [%0], [%1], 16;\n" :: "r"(dst), "l"(src));
}
#define CPA_COMMIT() asm volatile("cp.async.commit_group;\n" ::: "memory")
#define CPA_WAIT1()  asm volatile("cp.async.wait_group 1;\n" ::: "memory")
#define CPA_WAIT0()  asm volatile("cp.async.wait_group 0;\n" ::: "memory")

#define N4_QK  (2 * Cc * Cc / 4)
#define N4_QKV (Ll * 3 * Cc * Cc / 4)
#define N4_PRJ (Ll * Cc * Cc / 4)

__global__ void w2h_all(const float* __restrict__ qkw, const float* __restrict__ qkvw,
                        const float* __restrict__ projw) {
    int i = blockIdx.x * 256 + threadIdx.x;
    const float* s;
    __half* d;
    int j = i;
    if (j < N4_QK) { s = qkw; d = g_qkw_h; }
    else if ((j -= N4_QK) < N4_QKV) { s = qkvw; d = g_qkvw_h; }
    else if ((j -= N4_QKV) < N4_PRJ) { s = projw; d = g_projw_h; }
    else return;
    float4 v = *(const float4*)&s[j * 4];
    __half2 h0 = __floats2half2_rn(v.x, v.y);
    __half2 h1 = __floats2half2_rn(v.z, v.w);
    uint2 u;
    u.x = *reinterpret_cast<unsigned*>(&h0);
    u.y = *reinterpret_cast<unsigned*>(&h1);
    *reinterpret_cast<uint2*>(&d[j * 4]) = u;
}

// 256-thread transpose: 32x32 tile, 4 rows/thread
__global__ void transpose_in(const float* __restrict__ x) {
    __shared__ float tile[32][33];
    int b = blockIdx.z;
    int c0 = blockIdx.y * 32, n0 = blockIdx.x * 32;
    int tx = threadIdx.x & 31, ty0 = (threadIdx.x >> 5) * 4;
    #pragma unroll
    for (int j = 0; j < 4; j++)
        tile[ty0 + j][tx] = x[(long)b * Cc * Nn + (long)(c0 + ty0 + j) * Nn + n0 + tx];
    __syncthreads();
    #pragma unroll
    for (int j = 0; j < 4; j++) {
        float v = tile[tx][ty0 + j];
        long o = ((long)b * Nn + n0 + ty0 + j) * Cc + c0 + tx;
        g_node[o] = v;
        g_node_h[o] = __float2half(v);
    }
}

__global__ void transpose_out(float* __restrict__ out) {
    __shared__ float tile[32][33];
    int b = blockIdx.z;
    int c0 = blockIdx.y * 32, n0 = blockIdx.x * 32;
    int tx = threadIdx.x & 31, ty0 = (threadIdx.x >> 5) * 4;
    #pragma unroll
    for (int j = 0; j < 4; j++)
        tile[ty0 + j][tx] = g_node[((long)b * Nn + n0 + ty0 + j) * Cc + c0 + tx];
    __syncthreads();
    #pragma unroll
    for (int j = 0; j < 4; j++)
        out[(long)b * Cc * Nn + (long)(c0 + ty0 + j) * Nn + n0 + tx] = tile[tx][ty0 + j];
}

// Generic 64x64-tile FP16 WMMA NT GEMM, fp32 accum, cp.async 2-stage (K-tile 64).
// 128 threads; high grid counts -> multiple CTAs/SM for latency hiding.
#define GSTG64 18432
__global__ void gemm64(const __half* __restrict__ A, const __half* __restrict__ W,
                       const float* __restrict__ bias, void* __restrict__ Cout,
                       int K, int lda, int ldw, int ldc,
                       long sA, long sW, long sC, float alpha, int outHalf) {
    extern __shared__ char gsm[];
    int z = blockIdx.z;
    A += (long)z * sA; W += (long)z * sW;
    int bm = blockIdx.y * 64, bn = blockIdx.x * 64;
    int tid = threadIdx.x;  // 128
    int w = tid >> 5, wm = w >> 1, wn = w & 1;
    wmma::fragment<wmma::accumulator, 16, 16, 16, float> c[2][2];
    #pragma unroll
    for (int i = 0; i < 2; i++)
        #pragma unroll
        for (int j = 0; j < 2; j++) wmma::fill_fragment(c[i][j], 0.f);
    unsigned smbase = (unsigned)__cvta_generic_to_shared(gsm);
    auto loadStage = [&](int k0, int s) {
        unsigned base = smbase + s * GSTG64;
        #pragma unroll
        for (int i = 0; i < 4; i++) {
            int idx = tid + i * 128, r = idx >> 3, c8 = (idx & 7) * 8;
            cpa16(base + r * 144 + c8 * 2, &A[(long)(bm + r) * lda + k0 + c8]);
        }
        #pragma unroll
        for (int i = 0; i < 4; i++) {
            int idx = tid + i * 128, r = idx >> 3, c8 = (idx & 7) * 8;
            cpa16(base + 9216 + r * 144 + c8 * 2, &W[(long)(bn + r) * ldw + k0 + c8]);
        }
        CPA_COMMIT();
    };
    int nIter = K >> 6;
    loadStage(0, 0);
    for (int k = 0; k < nIter; k++) {
        if (k + 1 < nIter) { loadStage((k + 1) * 64, (k + 1) & 1); CPA_WAIT1(); }
        else CPA_WAIT0();
        __syncthreads();
        __half (*As)[72] = (__half(*)[72])(gsm + (k & 1) * GSTG64);
        __half (*Ws)[72] = (__half(*)[72])(gsm + (k & 1) * GSTG64 + 9216);
        #pragma unroll
        for (int kk = 0; kk < 4; kk++) {
            wmma::fragment<wmma::matrix_a, 16, 16, 16, __half, wmma::row_major> a[2];
            wmma::fragment<wmma::matrix_b, 16, 16, 16, __half, wmma::col_major> bf[2];
            #pragma unroll
            for (int i = 0; i < 2; i++)
                wmma::load_matrix_sync(a[i], &As[wm * 32 + i * 16][kk * 16], 72);
            #pragma unroll
            for (int j = 0; j < 2; j++)
                wmma::load_matrix_sync(bf[j], &Ws[wn * 32 + j * 16][kk * 16], 72);
            #pragma unroll
            for (int i = 0; i < 2; i++)
                #pragma unroll
                for (int j = 0; j < 2; j++) wmma::mma_sync(c[i][j], a[i], bf[j], c[i][j]);
        }
        __syncthreads();
    }
    float (*Cs)[68] = (float(*)[68])gsm;  // 64x68 fp32 = 17408 B
    #pragma unroll
    for (int i = 0; i < 2; i++)
        #pragma unroll
        for (int j = 0; j < 2; j++) {
            #pragma unroll
            for (int e = 0; e < c[i][j].num_elements; e++) c[i][j].x[e] *= alpha;
            wmma::store_matrix_sync(&Cs[wm * 32 + i * 16][wn * 32 + j * 16],
                                    c[i][j], 68, wmma::mem_row_major);
        }
    __syncthreads();
    if (outHalf) {
        __half* Ch = (__half*)Cout + (long)z * sC;
        #pragma unroll
        for (int i = 0; i < 8; i++) {
            int idx = tid + i * 128, r = idx >> 4, c4 = (idx & 15) * 4;
            float4 v = *(float4*)&Cs[r][c4];
            if (bias) {
                float4 bb = *(const float4*)&bias[bn + c4];
                v.x += bb.x; v.y += bb.y; v.z += bb.z; v.w += bb.w;
            }
            __half2 h0 = __floats2half2_rn(v.x, v.y);
            __half2 h1 = __floats2half2_rn(v.z, v.w);
            uint2 u;
            u.x = *reinterpret_cast<unsigned*>(&h0);
            u.y = *reinterpret_cast<unsigned*>(&h1);
            *reinterpret_cast<uint2*>(&Ch[(long)(bm + r) * ldc + bn + c4]) = u;
        }
    } else {
        float* Cf = (float*)Cout + (long)z * sC;
        #pragma unroll
        for (int i = 0; i < 8; i++) {
            int idx = tid + i * 128, r = idx >> 4, c4 = (idx & 15) * 4;
            float4 v = *(float4*)&Cs[r][c4];
            if (bias) {
                float4 bb = *(const float4*)&bias[bn + c4];
                v.x += bb.x; v.y += bb.y; v.z += bb.z; v.w += bb.w;
            }
            *(float4*)&Cf[(long)(bm + r) * ldc + bn + c4] = v;
        }
    }
}

// fused: blocks [0,256): warp-per-row edge softmax; blocks [256,258): fcp
__global__ void edgesm_fcp(const float* __restrict__ da, const float* __restrict__ fw,
                           const float* __restrict__ fb) {
    __shared__ float t[64];
    if (blockIdx.x < 256) {
        int row = blockIdx.x * 8 + (threadIdx.x >> 5);
        int lane = threadIdx.x & 31;
        float* p = g_edge + (long)row * Nn;
        float4 r[8];
        float mx = -INFINITY;
        #pragma unroll
        for (int k = 0; k < 8; k++) {
            r[k] = *(float4*)&p[lane * 4 + k * 128];
            mx = fmaxf(mx, fmaxf(fmaxf(r[k].x, r[k].y), fmaxf(r[k].z, r[k].w)));
        }
        #pragma unroll
        for (int o = 16; o > 0; o >>= 1) mx = fmaxf(mx, __shfl_xor_sync(0xffffffffu, mx, o));
        float Z = 0.f;
        #pragma unroll
        for (int k = 0; k < 8; k++) {
            r[k].x = __expf(r[k].x - mx); r[k].y = __expf(r[k].y - mx);
            r[k].z = __expf(r[k].z - mx); r[k].w = __expf(r[k].w - mx);
            Z += r[k].x + r[k].y + r[k].z + r[k].w;
        }
        #pragma unroll
        for (int o = 16; o > 0; o >>= 1) Z += __shfl_xor_sync(0xffffffffu, Z, o);
        float inv = 1.f / Z;
        #pragma unroll
        for (int k = 0; k < 8; k++) {
            r[k].x *= inv; r[k].y *= inv; r[k].z *= inv; r[k].w *= inv;
            *(float4*)&p[lane * 4 + k * 128] = r[k];
        }
    } else {
        int b = blockIdx.x - 256;
        int tid = threadIdx.x;
        if (tid < 64) {
            float s = 0.f;
            #pragma unroll
            for (int a = 0; a < 16; a++) s += da[(long)b * 16 * 64 + a * 64 + tid];
            t[tid] = s;
        }
        __syncthreads();
        for (int c = tid; c < Cc; c += 256) {
            float s = 16.f * fb[c];
            #pragma unroll
            for (int e = 0; e < 64; e++) s += t[e] * fw[c * 64 + e];
            g_s[b * Cc + c] = s;
        }
    }
}

// warp-per-row LN1 -> gate -> LN2, writes y as fp16.
__global__ void norm_kernel(const float* __restrict__ g1, const float* __restrict__ b1,
                            const float* __restrict__ g2, const float* __restrict__ b2) {
    int bn = blockIdx.x * 8 + (threadIdx.x >> 5);
    int b = bn >> 10, n = bn & 1023;
    int lane = threadIdx.x & 31;
    const float* xp = g_node + (long)bn * Cc;
    float x[10];
    float s = 0.f;
    #pragma unroll
    for (int j = 0; j < 10; j++) { x[j] = xp[lane + j * 32]; s += x[j]; }
    #pragma unroll
    for (int o = 16; o > 0; o >>= 1) s += __shfl_xor_sync(0xffffffffu, s, o);
    float mean = s * (1.f / Cc);
    float v = 0.f;
    #pragma unroll
    for (int j = 0; j < 10; j++) { x[j] -= mean; v += x[j] * x[j]; }
    #pragma unroll
    for (int o = 16; o > 0; o >>= 1) v += __shfl_xor_sync(0xffffffffu, v, o);
    float rstd = rsqrtf(v * (1.f / Cc) + EPS);
    float diag = g_edge[(long)b * Nn * Nn + (long)n * Nn + n];
    const float* gsp = g_s + b * Cc;
    float y[10];
    float s2 = 0.f;
    #pragma unroll
    for (int j = 0; j < 10; j++) {
        int c = lane + j * 32;
        float nt = x[j] * rstd * g1[c] + b1[c];
        y[j] = diag * nt * gsp[c] + nt;
        s2 += y[j];
    }
    #pragma unroll
    for (int o = 16; o > 0; o >>= 1) s2 += __shfl_xor_sync(0xffffffffu, s2, o);
    float mean2 = s2 * (1.f / Cc);
    float v2 = 0.f;
    #pragma unroll
    for (int j = 0; j < 10; j++) { y[j] -= mean2; v2 += y[j] * y[j]; }
    #pragma unroll
    for (int o = 16; o > 0; o >>= 1) v2 += __shfl_xor_sync(0xffffffffu, v2, o);
    float rstd2 = rsqrtf(v2 * (1.f / Cc) + EPS);
    __half* yp = g_y_h + (long)bn * Cc;
    #pragma unroll
    for (int j = 0; j < 10; j++) {
        int c = lane + j * 32;
        yp[c] = __float2half(y[j] * rstd2 * g2[c] + b2[c]);
    }
}

// attn scores (fp16 WMMA): RAW QK^T*ATT_SCALE -> g_sattn. 128x128 tiles.
__global__ void attn_score_half(void) {
    __shared__ char smraw[34816];
    __half (*Qs)[48] = (__half(*)[48])smraw;
    __half (*Ks)[48] = (__half(*)[48])(smraw + 12288);
    float (*Cs)[68] = (float(*)[68])smraw;
    int bh = blockIdx.z;
    int b = bh >> 3, h = bh & 7;
    int n0 = blockIdx.y * 128, m0 = blockIdx.x * 128;
    const __half* Qb = g_qkv_h + (long)b * Nn * 960 + h * DHh;
    const __half* Kb = Qb + Cc;
    int tid = threadIdx.x;  // 256
    for (int idx = tid; idx < 1024; idx += 256) {
        Qs[idx >> 3][40 + (idx & 7)] = __float2half(0.f);
        Ks[idx >> 3][40 + (idx & 7)] = __float2half(0.f);
    }
    for (int idx = tid; idx < 640; idx += 256) {
        int r = idx / 5, c8 = (idx % 5) * 8;
        *(uint4*)&Qs[r][c8] = *(const uint4*)&Qb[(long)(n0 + r) * 960 + c8];
        *(uint4*)&Ks[r][c8] = *(const uint4*)&Kb[(long)(m0 + r) * 960 + c8];
    }
    __syncthreads();
    int w = tid >> 5, wr = w >> 1, wc = w & 1;
    wmma::fragment<wmma::accumulator, 16, 16, 16, float> c[2][4];
    #pragma unroll
    for (int i = 0; i < 2; i++)
        #pragma unroll
        for (int j = 0; j < 4; j++) wmma::fill_fragment(c[i][j], 0.f);
    #pragma unroll
    for (int kk = 0; kk < 3; kk++) {
        wmma::fragment<wmma::matrix_a, 16, 16, 16, __half, wmma::row_major> a[2];
        wmma::fragment<wmma::matrix_b, 16, 16, 16, __half, wmma::col_major> bf[4];
        #pragma unroll
        for (int i = 0; i < 2; i++)
            wmma::load_matrix_sync(a[i], &Qs[wr * 32 + i * 16][kk * 16], 48);
        #pragma unroll
        for (int j = 0; j < 4; j++)
            wmma::load_matrix_sync(bf[j], &Ks[wc * 64 + j * 16][kk * 16], 48);
        #pragma unroll
        for (int i = 0; i < 2; i++)
            #pragma unroll
            for (int j = 0; j < 4; j++) wmma::mma_sync(c[i][j], a[i], bf[j], c[i][j]);
    }
    #pragma unroll
    for (int i = 0; i < 2; i++)
        #pragma unroll
        for (int j = 0; j < 4; j++)
            #pragma unroll
            for (int e = 0; e < c[i][j].num_elements; e++) c[i][j].x[e] *= ATT_SCALE;
    __half* op = g_sattn + ((long)b * NHh + h) * Nn * Nn;
    #pragma unroll
    for (int half = 0; half < 2; half++) {
        __syncthreads();
        if (wc == half) {
            #pragma unroll
            for (int i = 0; i < 2; i++)
                #pragma unroll
                for (int j = 0; j < 4; j++)
                    wmma::store_matrix_sync(&Cs[wr * 32 + i * 16][j * 16], c[i][j], 68,
                                            wmma::mem_row_major);
        }
        __syncthreads();
        #pragma unroll
        for (int i2 = 0; i2 < 8; i2++) {
            int idx = tid + i2 * 256;
            int r = idx >> 4, c4 = (idx & 15) * 4;
            float4 s = *(float4*)&Cs[r][c4];
            *(__half2*)&op[(long)(n0 + r) * Nn + m0 + half * 64 + c4]     = __floats2half2_rn(s.x, s.y);
            *(__half2*)&op[(long)(n0 + r) * Nn + m0 + half * 64 + c4 + 2] = __floats2half2_rn(s.z, s.w);
        }
    }
}

__device__ __forceinline__ void mergeTriple(float& m, float& z, float& s,
                                            float mo, float zo, float so) {
    float nm = fmaxf(m, mo);
    float f1 = __expf(m - nm), f2 = __expf(mo - nm);
    z = z * f1 + zo * f2;
    s = s * f1 + so * f2;
    m = nm;
}

// warp-per-head softmax + edge_new + edge update + wsum (probs in-place, uint4 I/O)
__global__ void softmax_ednew(const float* __restrict__ exp_w, const float* __restrict__ exp_b,
                              const float* __restrict__ red_w, const float* __restrict__ red_b) {
    __shared__ float es[Nn];
    __shared__ float Ts[NHh][Nn];
    __shared__ float red3[24];
    int bn = blockIdx.x;
    int b = bn >> 10, n = bn & 1023;
    int tid = threadIdx.x;
    int w = tid >> 5, lane = tid & 31;
    __half* Ab = g_sattn + (((long)b * NHh + w) * Nn + n) * Nn;
    float* ep = g_edge + (long)b * Nn * Nn + (long)n * Nn;
    *(float4*)&es[tid * 4] = *(const float4*)&ep[tid * 4];
    __syncthreads();
    float ew = exp_w[w], eb = exp_b[w], rw = red_w[w];

    float4 r[8], e[8];
    #pragma unroll
    for (int k = 0; k < 4; k++) {
        uint4 u = *(const uint4*)&Ab[lane * 8 + k * 256];
        float2 fa = __half22float2(*(__half2*)&u.x);
        float2 fb2 = __half22float2(*(__half2*)&u.y);
        float2 fc = __half22float2(*(__half2*)&u.z);
        float2 fd = __half22float2(*(__half2*)&u.w);
        float4 ev0 = *(float4*)&es[lane * 8 + k * 256];
        float4 ev1 = *(float4*)&es[lane * 8 + k * 256 + 4];
        r[2 * k].x     = fa.x + ev0.x * ew + eb;
        r[2 * k].y     = fa.y + ev0.y * ew + eb;
        r[2 * k].z     = fb2.x + ev0.z * ew + eb;
        r[2 * k].w     = fb2.y + ev0.w * ew + eb;
        r[2 * k + 1].x = fc.x + ev1.x * ew + eb;
        r[2 * k + 1].y = fc.y + ev1.y * ew + eb;
        r[2 * k + 1].z = fd.x + ev1.z * ew + eb;
        r[2 * k + 1].w = fd.y + ev1.w * ew + eb;
    }
    float M = -INFINITY;
    #pragma unroll
    for (int k = 0; k < 8; k++)
        M = fmaxf(M, fmaxf(fmaxf(r[k].x, r[k].y), fmaxf(r[k].z, r[k].w)));
    #pragma unroll
    for (int o = 16; o > 0; o >>= 1) M = fmaxf(M, __shfl_xor_sync(0xffffffffu, M, o));
    float Z = 0.f;
    #pragma unroll
    for (int k = 0; k < 8; k++) {
        e[k].x = __expf(r[k].x - M); e[k].y = __expf(r[k].y - M);
        e[k].z = __expf(r[k].z - M); e[k].w = __expf(r[k].w - M);
        Z += e[k].x + e[k].y + e[k].z + e[k].w;
    }
    #pragma unroll
    for (int o = 16; o > 0; o >>= 1) Z += __shfl_xor_sync(0xffffffffu, Z, o);
    float inv = 1.f / Z;
    #pragma unroll
    for (int k = 0; k < 4; k++) {
        float4 a0, a1;
        a0.x = e[2 * k].x * inv;     a0.y = e[2 * k].y * inv;
        a0.z = e[2 * k].z * inv;     a0.w = e[2 * k].w * inv;
        a1.x = e[2 * k + 1].x * inv; a1.y = e[2 * k + 1].y * inv;
        a1.z = e[2 * k + 1].z * inv; a1.w = e[2 * k + 1].w * inv;
        uint4 u;
        __half2 p0 = __floats2half2_rn(a0.x, a0.y);
        __half2 p1 = __floats2half2_rn(a0.z, a0.w);
        __half2 p2 = __floats2half2_rn(a1.x, a1.y);
        __half2 p3 = __floats2half2_rn(a1.z, a1.w);
        u.x = *reinterpret_cast<unsigned*>(&p0);
        u.y = *reinterpret_cast<unsigned*>(&p1);
        u.z = *reinterpret_cast<unsigned*>(&p2);
        u.w = *reinterpret_cast<unsigned*>(&p3);
        *(uint4*)&Ab[lane * 8 + k * 256] = u;
        float4 t0, t1;
        t0.x = rw * (a0.x + r[2 * k].x); t0.y = rw * (a0.y + r[2 * k].y);
        t0.z = rw * (a0.z + r[2 * k].z); t0.w = rw * (a0.w + r[2 * k].w);
        t1.x = rw * (a1.x + r[2 * k + 1].x); t1.y = rw * (a1.y + r[2 * k + 1].y);
        t1.z = rw * (a1.z + r[2 * k + 1].z); t1.w = rw * (a1.w + r[2 * k + 1].w);
        *(float4*)&Ts[w][lane * 8 + k * 256]     = t0;
        *(float4*)&Ts[w][lane * 8 + k * 256 + 4] = t1;
    }
    __syncthreads();

    float rb = red_b[0];
    float4 en = {rb, rb, rb, rb};
    #pragma unroll
    for (int h = 0; h < NHh; h++) {
        float4 t = *(float4*)&Ts[h][tid * 4];
        en.x += t.x; en.y += t.y; en.z += t.z; en.w += t.w;
    }
    float4 ec = *(float4*)&es[tid * 4];
    ec.x += en.x; ec.y += en.y; ec.z += en.z; ec.w += en.w;
    *(float4*)&ep[tid * 4] = ec;
    float m2 = fmaxf(fmaxf(en.x, en.y), fmaxf(en.z, en.w));
    float f0 = __expf(en.x - m2), f1 = __expf(en.y - m2),
          f2 = __expf(en.z - m2), f3 = __expf(en.w - m2);
    float z2 = f0 + f1 + f2 + f3;
    float s2 = f0 * en.x + f1 * en.y + f2 * en.z + f3 * en.w;
    #pragma unroll
    for (int o = 16; o > 0; o >>= 1)
        mergeTriple(m2, z2, s2,
                    __shfl_xor_sync(0xffffffffu, m2, o),
                    __shfl_xor_sync(0xffffffffu, z2, o),
                    __shfl_xor_sync(0xffffffffu, s2, o));
    if (lane == 0) { red3[w * 3] = m2; red3[w * 3 + 1] = z2; red3[w * 3 + 2] = s2; }
    __syncthreads();
    if (tid < 32) {
        float mm = (lane < 8) ? red3[lane * 3]     : -INFINITY;
        float zz = (lane < 8) ? red3[lane * 3 + 1] : 0.f;
        float ss = (lane < 8) ? red3[lane * 3 + 2] : 0.f;
        #pragma unroll
        for (int o = 4; o > 0; o >>= 1)
            mergeTriple(mm, zz, ss,
                        __shfl_xor_sync(0xffffffffu, mm, o),
                        __shfl_xor_sync(0xffffffffu, zz, o),
                        __shfl_xor_sync(0xffffffffu, ss, o));
        if (lane == 0) g_wsum[bn] = ss / zz;
    }
}

// AV (fp16 WMMA): 32-row n-tiles (grid 512), 128 thr, cp.async 2-stage,
// in-block kk-split: warp w -> rows (w&1)*16, kk pair (w>>1). Partials merged in smem.
#define AV32STG 10752   // P 32x144 (4608) + V 64x48 halves (6144)
__global__ void av_half(void) {
    extern __shared__ char avsm[];
    int bh = blockIdx.y;
    int b = bh >> 3, h = bh & 7;
    int n0 = blockIdx.x * 32;
    int tid = threadIdx.x;  // 128
    int w = tid >> 5;
    int g = w & 1;          // row group (16 rows)
    int kg = w >> 1;        // kk half (0: kk 0-1, 1: kk 2-3)
    const __half* Pb = g_sattn + (((long)b * NHh + h) * Nn + n0) * Nn;
    const __half* Vb = g_qkv_h + (long)b * Nn * 960 + 640 + h * DHh;
    unsigned smbase = (unsigned)__cvta_generic_to_shared(avsm);
    for (int s = 0; s < 2; s++) {
        __half* vp = (__half*)(avsm + s * AV32STG + 4608);
        for (int idx = tid; idx < 512; idx += 128) vp[(idx >> 3) * 48 + 40 + (idx & 7)] = __float2half(0.f);
    }
    wmma::fragment<wmma::accumulator, 16, 16, 16, float> c[3];
    #pragma unroll
    for (int j = 0; j < 3; j++) wmma::fill_fragment(c[j], 0.f);
    auto loadStage = [&](int m0, int s) {
        unsigned base = smbase + s * AV32STG;
        #pragma unroll
        for (int i = 0; i < 2; i++) {  // P: 32 rows x 8 chunks = 256
            int idx = tid + i * 128, r = idx >> 3, c8 = (idx & 7) * 8;
            cpa16(base + r * 144 + c8 * 2, &Pb[(long)r * Nn + m0 + c8]);
        }
        #pragma unroll
        for (int i = 0; i < 3; i++) {  // V: 64 rows x 5 chunks = 320
            int idx = tid + i * 128;
            if (idx < 320) {
                int r = idx / 5, c8 = (idx % 5) * 8;
                cpa16(base + 4608 + r * 96 + c8 * 2, &Vb[(long)(m0 + r) * 960 + c8]);
            }
        }
        CPA_COMMIT();
    };
    loadStage(0, 0);
    for (int k = 0; k < 16; k++) {
        if (k + 1 < 16) { loadStage((k + 1) * 64, (k + 1) & 1); CPA_WAIT1(); }
        else CPA_WAIT0();
        __syncthreads();
        __half (*Ps)[72] = (__half(*)[72])(avsm + (k & 1) * AV32STG);
        __half (*Vs)[48] = (__half(*)[48])(avsm + (k & 1) * AV32STG + 4608);
        #pragma unroll
        for (int kk2 = 0; kk2 < 2; kk2++) {
            int kk = kg * 2 + kk2;
            wmma::fragment<wmma::matrix_a, 16, 16, 16, __half, wmma::row_major> a;
            wmma::load_matrix_sync(a, &Ps[g * 16][kk * 16], 72);
            #pragma unroll
            for (int j = 0; j < 3; j++) {
                wmma::fragment<wmma::matrix_b, 16, 16, 16, __half, wmma::row_major> bf;
                wmma::load_matrix_sync(bf, &Vs[kk * 16][j * 16], 48);
                wmma::mma_sync(c[j], a, bf, c[j]);
            }
        }
        __syncthreads();
    }
    // merge partials: each warp stores its 16x48 partial, then add kg=0 + kg=1
    float* Cbase = (float*)avsm;  // 4 warps x 16x48 fp32 = 12288 B (stages dead)
    #pragma unroll
    for (int j = 0; j < 3; j++)
        wmma::store_matrix_sync(Cbase + w * 768 + j * 16, c[j], 48, wmma::mem_row_major);
    __syncthreads();
    const float* wsp = g_wsum + b * Nn + n0;
    __half* op = g_nodeout_h + ((long)b * Nn + n0) * Cc + h * DHh;
    for (int idx = tid; idx < 320; idx += 128) {  // 32 rows x 10 f4-chunks
        int r = idx / 10, c4 = (idx % 10) * 4;
        int g2 = r >> 4, r16 = r & 15;
        float4 v0 = *(float4*)&Cbase[g2 * 768 + r16 * 48 + c4];
        float4 v1 = *(float4*)&Cbase[(2 + g2) * 768 + r16 * 48 + c4];
        float wv = wsp[r];
        __half2 h0 = __floats2half2_rn(v0.x + v1.x + wv, v0.y + v1.y + wv);
        __half2 h1 = __floats2half2_rn(v0.z + v1.z + wv, v0.w + v1.w + wv);
        uint2 u;
        u.x = *reinterpret_cast<unsigned*>(&h0);
        u.y = *reinterpret_cast<unsigned*>(&h1);
        *reinterpret_cast<uint2*>(&op[(long)r * Cc + c4]) = u;
    }
}

static void* symv(const void* s) {
    void* p = nullptr;
    cudaGetSymbolAddress(&p, s);
    return p;
}

extern "C" void kernel_launch(void* const* d_in, const int* in_sizes, int n_in,
                              void* d_out, int out_size) {
    const float* x        = (const float*)d_in[0];
    const float* da_prior = (const float*)d_in[1];
    const float* qk_w     = (const float*)d_in[2];
    const float* fcp_w    = (const float*)d_in[3];
    const float* fcp_b    = (const float*)d_in[4];
    const float* ln1_g    = (const float*)d_in[5];
    const float* ln1_b    = (const float*)d_in[6];
    const float* gln_g    = (const float*)d_in[7];
    const float* gln_b    = (const float*)d_in[8];
    const float* qkv_w    = (const float*)d_in[9];
    const float* qkv_b    = (const float*)d_in[10];
    const float* proj_w   = (const float*)d_in[11];
    const float* proj_b   = (const float*)d_in[12];
    const float* exp_w    = (const float*)d_in[13];
    const float* exp_b    = (const float*)d_in[14];
    const float* red_w    = (const float*)d_in[15];
    const float* red_b    = (const float*)d_in[16];
    float* out = (float*)d_out;

    float*  p_node   = (float*)symv(g_node);
    float*  p_edge   = (float*)symv(g_edge);
    __half* p_node_h = (__half*)symv(g_node_h);
    __half* p_qk2_h  = (__half*)symv(g_qk2_h);
    __half* p_y_h    = (__half*)symv(g_y_h);
    __half* p_qkv_h  = (__half*)symv(g_qkv_h);
    __half* p_no_h   = (__half*)symv(g_nodeout_h);
    __half* p_qkw_h  = (__half*)symv(g_qkw_h);
    __half* p_qkvw_h = (__half*)symv(g_qkvw_h);
    __half* p_projw_h= (__half*)symv(g_projw_h);

    cudaFuncSetAttribute(gemm64, cudaFuncAttributeMaxDynamicSharedMemorySize, 2 * GSTG64);
    cudaFuncSetAttribute(av_half, cudaFuncAttributeMaxDynamicSharedMemorySize, 2 * AV32STG);

    w2h_all<<<(N4_QK + N4_QKV + N4_PRJ + 255) / 256, 256>>>(qk_w, qkv_w, proj_w);
    transpose_in<<<dim3(32, 10, Bb), 256>>>(x);
    // qe|ke = node @ qk_w^T -> half  (grid 320)
    gemm64<<<dim3(10, 32, 1), 128, 2 * GSTG64>>>(p_node_h, p_qkw_h, nullptr, p_qk2_h,
                                                 Cc, Cc, Cc, 2 * Cc, 0, 0, 0, 1.f, 1);
    // edge = qe @ ke^T * EDGE_SCALE -> fp32, per batch  (grid 512)
    gemm64<<<dim3(16, 16, Bb), 128, 2 * GSTG64>>>(p_qk2_h, p_qk2_h + Cc, nullptr, p_edge,
                                                  Cc, 2 * Cc, 2 * Cc, Nn,
                                                  (long)Nn * 2 * Cc, (long)Nn * 2 * Cc,
                                                  (long)Nn * Nn, EDGE_SCALE, 0);
    edgesm_fcp<<<258, 256>>>(da_prior, fcp_w, fcp_b);

    for (int l = 0; l < Ll; l++) {
        norm_kernel<<<Bb * Nn / 8, 256>>>(ln1_g + l * Cc, ln1_b + l * Cc,
                                          gln_g + l * Cc, gln_b + l * Cc);
        // qkv  (grid 480)
        gemm64<<<dim3(15, 32, 1), 128, 2 * GSTG64>>>(p_y_h, p_qkvw_h + (long)l * 3 * Cc * Cc,
                                                     qkv_b + l * 3 * Cc, p_qkv_h,
                                                     Cc, Cc, Cc, 3 * Cc, 0, 0, 0, 1.f, 1);
        attn_score_half<<<dim3(8, 8, Bb * NHh), 256>>>();
        softmax_ednew<<<Bb * Nn, 256>>>(exp_w + l * NHh, exp_b + l * NHh,
                                        red_w + l * NHh, red_b + l);
        av_half<<<dim3(32, Bb * NHh), 128, 2 * AV32STG>>>();
        // proj  (grid 160)
        gemm64<<<dim3(5, 32, 1), 128, 2 * GSTG64>>>(p_no_h, p_projw_h + (long)l * Cc * Cc,
                                                    proj_b + l * Cc, p_node,
                                                    Cc, Cc, Cc, Cc, 0, 0, 0, 1.f, 0);
    }
    transpose_out<<<dim3(32, 10, Bb), 256>>>(out);
}

// round 17
// speedup vs baseline: 1.0814x; 1.0480x over previous
#include <cuda_runtime.h>
#include <cuda_fp16.h>
#include <mma.h>
#include <math.h>

using namespace nvcuda;

#define Bb 2
#define Cc 320
#define Nn 1024
#define NHh 8
#define DHh 40
#define Ll 2
#define EPS 1e-5f
#define EDGE_SCALE 0.17677669529663687f
#define ATT_SCALE  0.15811388300841897f

// fp32 state
__device__ float g_node[Bb * Nn * Cc];
__device__ float g_edge[Bb * Nn * Nn];
__device__ float g_s[Bb * Cc];
__device__ float g_wsum[Bb * Nn];
// fp16-resident dataflow
__device__ __half g_node_h[Bb * Nn * Cc];
__device__ __half g_qk2_h[Bb * Nn * 2 * Cc];
__device__ __half g_y_h[Bb * Nn * Cc];
__device__ __half g_qkv_h[Bb * Nn * 3 * Cc];
__device__ __half g_sattn[Bb * NHh * Nn * Nn];
__device__ __half g_nodeout_h[Bb * Nn * Cc];
// pre-converted weights
__device__ __half g_qkw_h[2 * Cc * Cc];
__device__ __half g_qkvw_h[Ll * 3 * Cc * Cc];
__device__ __half g_projw_h[Ll * Cc * Cc];

__device__ __forceinline__ void gdep(void) {
    cudaGridDependencySynchronize();
}

__device__ __forceinline__ void cpa16(unsigned dst, const void* src) {
    asm volatile("cp.async.cg.shared.global [%0], [%1], 16;\n" :: "r"(dst), "l"(src));
}
#define CPA_COMMIT() asm volatile("cp.async.commit_group;\n" ::: "memory")
#define CPA_WAIT1()  asm volatile("cp.async.wait_group 1;\n" ::: "memory")
#define CPA_WAIT0()  asm volatile("cp.async.wait_group 0;\n" ::: "memory")

#define N4_QK  (2 * Cc * Cc / 4)
#define N4_QKV (Ll * 3 * Cc * Cc / 4)
#define N4_PRJ (Ll * Cc * Cc / 4)

__global__ void w2h_all(const float* __restrict__ qkw, const float* __restrict__ qkvw,
                        const float* __restrict__ projw) {
    int i = blockIdx.x * 256 + threadIdx.x;
    const float* s;
    __half* d;
    int j = i;
    if (j < N4_QK) { s = qkw; d = g_qkw_h; }
    else if ((j -= N4_QK) < N4_QKV) { s = qkvw; d = g_qkvw_h; }
    else if ((j -= N4_QKV) < N4_PRJ) { s = projw; d = g_projw_h; }
    else return;
    gdep();
    float4 v = *(const float4*)&s[j * 4];
    __half2 h0 = __floats2half2_rn(v.x, v.y);
    __half2 h1 = __floats2half2_rn(v.z, v.w);
    uint2 u;
    u.x = *reinterpret_cast<unsigned*>(&h0);
    u.y = *reinterpret_cast<unsigned*>(&h1);
    *reinterpret_cast<uint2*>(&d[j * 4]) = u;
}

// 256-thread transpose: 32x32 tile, 4 rows/thread
__global__ void transpose_in(const float* __restrict__ x) {
    __shared__ float tile[32][33];
    int b = blockIdx.z;
    int c0 = blockIdx.y * 32, n0 = blockIdx.x * 32;
    int tx = threadIdx.x & 31, ty0 = (threadIdx.x >> 5) * 4;
    gdep();
    #pragma unroll
    for (int j = 0; j < 4; j++)
        tile[ty0 + j][tx] = x[(long)b * Cc * Nn + (long)(c0 + ty0 + j) * Nn + n0 + tx];
    __syncthreads();
    #pragma unroll
    for (int j = 0; j < 4; j++) {
        float v = tile[tx][ty0 + j];
        long o = ((long)b * Nn + n0 + ty0 + j) * Cc + c0 + tx;
        g_node[o] = v;
        g_node_h[o] = __float2half(v);
    }
}

__global__ void transpose_out(float* __restrict__ out) {
    __shared__ float tile[32][33];
    int b = blockIdx.z;
    int c0 = blockIdx.y * 32, n0 = blockIdx.x * 32;
    int tx = threadIdx.x & 31, ty0 = (threadIdx.x >> 5) * 4;
    gdep();
    #pragma unroll
    for (int j = 0; j < 4; j++)
        tile[ty0 + j][tx] = g_node[((long)b * Nn + n0 + ty0 + j) * Cc + c0 + tx];
    __syncthreads();
    #pragma unroll
    for (int j = 0; j < 4; j++)
        out[(long)b * Cc * Nn + (long)(c0 + ty0 + j) * Nn + n0 + tx] = tile[tx][ty0 + j];
}

// Generic 64x64-tile FP16 WMMA NT GEMM, fp32 accum, cp.async 2-stage (K-tile 64).
#define GSTG64 18432
__global__ void gemm64(const __half* __restrict__ A, const __half* __restrict__ W,
                       const float* __restrict__ bias, void* __restrict__ Cout,
                       int K, int lda, int ldw, int ldc,
                       long sA, long sW, long sC, float alpha, int outHalf) {
    extern __shared__ char gsm[];
    int z = blockIdx.z;
    A += (long)z * sA; W += (long)z * sW;
    int bm = blockIdx.y * 64, bn = blockIdx.x * 64;
    int tid = threadIdx.x;  // 128
    int w = tid >> 5, wm = w >> 1, wn = w & 1;
    wmma::fragment<wmma::accumulator, 16, 16, 16, float> c[2][2];
    #pragma unroll
    for (int i = 0; i < 2; i++)
        #pragma unroll
        for (int j = 0; j < 2; j++) wmma::fill_fragment(c[i][j], 0.f);
    unsigned smbase = (unsigned)__cvta_generic_to_shared(gsm);
    auto loadStage = [&](int k0, int s) {
        unsigned base = smbase + s * GSTG64;
        #pragma unroll
        for (int i = 0; i < 4; i++) {
            int idx = tid + i * 128, r = idx >> 3, c8 = (idx & 7) * 8;
            cpa16(base + r * 144 + c8 * 2, &A[(long)(bm + r) * lda + k0 + c8]);
        }
        #pragma unroll
        for (int i = 0; i < 4; i++) {
            int idx = tid + i * 128, r = idx >> 3, c8 = (idx & 7) * 8;
            cpa16(base + 9216 + r * 144 + c8 * 2, &W[(long)(bn + r) * ldw + k0 + c8]);
        }
        CPA_COMMIT();
    };
    gdep();
    int nIter = K >> 6;
    loadStage(0, 0);
    for (int k = 0; k < nIter; k++) {
        if (k + 1 < nIter) { loadStage((k + 1) * 64, (k + 1) & 1); CPA_WAIT1(); }
        else CPA_WAIT0();
        __syncthreads();
        __half (*As)[72] = (__half(*)[72])(gsm + (k & 1) * GSTG64);
        __half (*Ws)[72] = (__half(*)[72])(gsm + (k & 1) * GSTG64 + 9216);
        #pragma unroll
        for (int kk = 0; kk < 4; kk++) {
            wmma::fragment<wmma::matrix_a, 16, 16, 16, __half, wmma::row_major> a[2];
            wmma::fragment<wmma::matrix_b, 16, 16, 16, __half, wmma::col_major> bf[2];
            #pragma unroll
            for (int i = 0; i < 2; i++)
                wmma::load_matrix_sync(a[i], &As[wm * 32 + i * 16][kk * 16], 72);
            #pragma unroll
            for (int j = 0; j < 2; j++)
                wmma::load_matrix_sync(bf[j], &Ws[wn * 32 + j * 16][kk * 16], 72);
            #pragma unroll
            for (int i = 0; i < 2; i++)
                #pragma unroll
                for (int j = 0; j < 2; j++) wmma::mma_sync(c[i][j], a[i], bf[j], c[i][j]);
        }
        __syncthreads();
    }
    float (*Cs)[68] = (float(*)[68])gsm;
    #pragma unroll
    for (int i = 0; i < 2; i++)
        #pragma unroll
        for (int j = 0; j < 2; j++) {
            #pragma unroll
            for (int e = 0; e < c[i][j].num_elements; e++) c[i][j].x[e] *= alpha;
            wmma::store_matrix_sync(&Cs[wm * 32 + i * 16][wn * 32 + j * 16],
                                    c[i][j], 68, wmma::mem_row_major);
        }
    __syncthreads();
    if (outHalf) {
        __half* Ch = (__half*)Cout + (long)z * sC;
        #pragma unroll
        for (int i = 0; i < 8; i++) {
            int idx = tid + i * 128, r = idx >> 4, c4 = (idx & 15) * 4;
            float4 v = *(float4*)&Cs[r][c4];
            if (bias) {
                float4 bb = *(const float4*)&bias[bn + c4];
                v.x += bb.x; v.y += bb.y; v.z += bb.z; v.w += bb.w;
            }
            __half2 h0 = __floats2half2_rn(v.x, v.y);
            __half2 h1 = __floats2half2_rn(v.z, v.w);
            uint2 u;
            u.x = *reinterpret_cast<unsigned*>(&h0);
            u.y = *reinterpret_cast<unsigned*>(&h1);
            *reinterpret_cast<uint2*>(&Ch[(long)(bm + r) * ldc + bn + c4]) = u;
        }
    } else {
        float* Cf = (float*)Cout + (long)z * sC;
        #pragma unroll
        for (int i = 0; i < 8; i++) {
            int idx = tid + i * 128, r = idx >> 4, c4 = (idx & 15) * 4;
            float4 v = *(float4*)&Cs[r][c4];
            if (bias) {
                float4 bb = *(const float4*)&bias[bn + c4];
                v.x += bb.x; v.y += bb.y; v.z += bb.z; v.w += bb.w;
            }
            *(float4*)&Cf[(long)(bm + r) * ldc + bn + c4] = v;
        }
    }
}

// fused: blocks [0,256): warp-per-row edge softmax; blocks [256,258): fcp
__global__ void edgesm_fcp(const float* __restrict__ da, const float* __restrict__ fw,
                           const float* __restrict__ fb) {
    __shared__ float t[64];
    gdep();
    if (blockIdx.x < 256) {
        int row = blockIdx.x * 8 + (threadIdx.x >> 5);
        int lane = threadIdx.x & 31;
        float* p = g_edge + (long)row * Nn;
        float4 r[8];
        float mx = -INFINITY;
        #pragma unroll
        for (int k = 0; k < 8; k++) {
            r[k] = *(float4*)&p[lane * 4 + k * 128];
            mx = fmaxf(mx, fmaxf(fmaxf(r[k].x, r[k].y), fmaxf(r[k].z, r[k].w)));
        }
        #pragma unroll
        for (int o = 16; o > 0; o >>= 1) mx = fmaxf(mx, __shfl_xor_sync(0xffffffffu, mx, o));
        float Z = 0.f;
        #pragma unroll
        for (int k = 0; k < 8; k++) {
            r[k].x = __expf(r[k].x - mx); r[k].y = __expf(r[k].y - mx);
            r[k].z = __expf(r[k].z - mx); r[k].w = __expf(r[k].w - mx);
            Z += r[k].x + r[k].y + r[k].z + r[k].w;
        }
        #pragma unroll
        for (int o = 16; o > 0; o >>= 1) Z += __shfl_xor_sync(0xffffffffu, Z, o);
        float inv = 1.f / Z;
        #pragma unroll
        for (int k = 0; k < 8; k++) {
            r[k].x *= inv; r[k].y *= inv; r[k].z *= inv; r[k].w *= inv;
            *(float4*)&p[lane * 4 + k * 128] = r[k];
        }
    } else {
        int b = blockIdx.x - 256;
        int tid = threadIdx.x;
        if (tid < 64) {
            float s = 0.f;
            #pragma unroll
            for (int a = 0; a < 16; a++) s += da[(long)b * 16 * 64 + a * 64 + tid];
            t[tid] = s;
        }
        __syncthreads();
        for (int c = tid; c < Cc; c += 256) {
            float s = 16.f * fb[c];
            #pragma unroll
            for (int e = 0; e < 64; e++) s += t[e] * fw[c * 64 + e];
            g_s[b * Cc + c] = s;
        }
    }
}

// warp-per-row LN1 -> gate -> LN2, writes y as fp16.
__global__ void norm_kernel(const float* __restrict__ g1, const float* __restrict__ b1,
                            const float* __restrict__ g2, const float* __restrict__ b2) {
    int bn = blockIdx.x * 8 + (threadIdx.x >> 5);
    int b = bn >> 10, n = bn & 1023;
    int lane = threadIdx.x & 31;
    gdep();
    const float* xp = g_node + (long)bn * Cc;
    float x[10];
    float s = 0.f;
    #pragma unroll
    for (int j = 0; j < 10; j++) { x[j] = xp[lane + j * 32]; s += x[j]; }
    #pragma unroll
    for (int o = 16; o > 0; o >>= 1) s += __shfl_xor_sync(0xffffffffu, s, o);
    float mean = s * (1.f / Cc);
    float v = 0.f;
    #pragma unroll
    for (int j = 0; j < 10; j++) { x[j] -= mean; v += x[j] * x[j]; }
    #pragma unroll
    for (int o = 16; o > 0; o >>= 1) v += __shfl_xor_sync(0xffffffffu, v, o);
    float rstd = rsqrtf(v * (1.f / Cc) + EPS);
    float diag = g_edge[(long)b * Nn * Nn + (long)n * Nn + n];
    const float* gsp = g_s + b * Cc;
    float y[10];
    float s2 = 0.f;
    #pragma unroll
    for (int j = 0; j < 10; j++) {
        int c = lane + j * 32;
        float nt = x[j] * rstd * g1[c] + b1[c];
        y[j] = diag * nt * gsp[c] + nt;
        s2 += y[j];
    }
    #pragma unroll
    for (int o = 16; o > 0; o >>= 1) s2 += __shfl_xor_sync(0xffffffffu, s2, o);
    float mean2 = s2 * (1.f / Cc);
    float v2 = 0.f;
    #pragma unroll
    for (int j = 0; j < 10; j++) { y[j] -= mean2; v2 += y[j] * y[j]; }
    #pragma unroll
    for (int o = 16; o > 0; o >>= 1) v2 += __shfl_xor_sync(0xffffffffu, v2, o);
    float rstd2 = rsqrtf(v2 * (1.f / Cc) + EPS);
    __half* yp = g_y_h + (long)bn * Cc;
    #pragma unroll
    for (int j = 0; j < 10; j++) {
        int c = lane + j * 32;
        yp[c] = __float2half(y[j] * rstd2 * g2[c] + b2[c]);
    }
}

// attn scores (fp16 WMMA): RAW QK^T*ATT_SCALE -> g_sattn. 128x128 tiles.
__global__ void attn_score_half(void) {
    __shared__ char smraw[34816];
    __half (*Qs)[48] = (__half(*)[48])smraw;
    __half (*Ks)[48] = (__half(*)[48])(smraw + 12288);
    float (*Cs)[68] = (float(*)[68])smraw;
    int bh = blockIdx.z;
    int b = bh >> 3, h = bh & 7;
    int n0 = blockIdx.y * 128, m0 = blockIdx.x * 128;
    const __half* Qb = g_qkv_h + (long)b * Nn * 960 + h * DHh;
    const __half* Kb = Qb + Cc;
    int tid = threadIdx.x;  // 256
    for (int idx = tid; idx < 1024; idx += 256) {
        Qs[idx >> 3][40 + (idx & 7)] = __float2half(0.f);
        Ks[idx >> 3][40 + (idx & 7)] = __float2half(0.f);
    }
    gdep();
    for (int idx = tid; idx < 640; idx += 256) {
        int r = idx / 5, c8 = (idx % 5) * 8;
        *(uint4*)&Qs[r][c8] = *(const uint4*)&Qb[(long)(n0 + r) * 960 + c8];
        *(uint4*)&Ks[r][c8] = *(const uint4*)&Kb[(long)(m0 + r) * 960 + c8];
    }
    __syncthreads();
    int w = tid >> 5, wr = w >> 1, wc = w & 1;
    wmma::fragment<wmma::accumulator, 16, 16, 16, float> c[2][4];
    #pragma unroll
    for (int i = 0; i < 2; i++)
        #pragma unroll
        for (int j = 0; j < 4; j++) wmma::fill_fragment(c[i][j], 0.f);
    #pragma unroll
    for (int kk = 0; kk < 3; kk++) {
        wmma::fragment<wmma::matrix_a, 16, 16, 16, __half, wmma::row_major> a[2];
        wmma::fragment<wmma::matrix_b, 16, 16, 16, __half, wmma::col_major> bf[4];
        #pragma unroll
        for (int i = 0; i < 2; i++)
            wmma::load_matrix_sync(a[i], &Qs[wr * 32 + i * 16][kk * 16], 48);
        #pragma unroll
        for (int j = 0; j < 4; j++)
            wmma::load_matrix_sync(bf[j], &Ks[wc * 64 + j * 16][kk * 16], 48);
        #pragma unroll
        for (int i = 0; i < 2; i++)
            #pragma unroll
            for (int j = 0; j < 4; j++) wmma::mma_sync(c[i][j], a[i], bf[j], c[i][j]);
    }
    #pragma unroll
    for (int i = 0; i < 2; i++)
        #pragma unroll
        for (int j = 0; j < 4; j++)
            #pragma unroll
            for (int e = 0; e < c[i][j].num_elements; e++) c[i][j].x[e] *= ATT_SCALE;
    __half* op = g_sattn + ((long)b * NHh + h) * Nn * Nn;
    #pragma unroll
    for (int half = 0; half < 2; half++) {
        __syncthreads();
        if (wc == half) {
            #pragma unroll
            for (int i = 0; i < 2; i++)
                #pragma unroll
                for (int j = 0; j < 4; j++)
                    wmma::store_matrix_sync(&Cs[wr * 32 + i * 16][j * 16], c[i][j], 68,
                                            wmma::mem_row_major);
        }
        __syncthreads();
        #pragma unroll
        for (int i2 = 0; i2 < 8; i2++) {
            int idx = tid + i2 * 256;
            int r = idx >> 4, c4 = (idx & 15) * 4;
            float4 s = *(float4*)&Cs[r][c4];
            *(__half2*)&op[(long)(n0 + r) * Nn + m0 + half * 64 + c4]     = __floats2half2_rn(s.x, s.y);
            *(__half2*)&op[(long)(n0 + r) * Nn + m0 + half * 64 + c4 + 2] = __floats2half2_rn(s.z, s.w);
        }
    }
}

__device__ __forceinline__ void mergeTriple(float& m, float& z, float& s,
                                            float mo, float zo, float so) {
    float nm = fmaxf(m, mo);
    float f1 = __expf(m - nm), f2 = __expf(mo - nm);
    z = z * f1 + zo * f2;
    s = s * f1 + so * f2;
    m = nm;
}

// warp-per-head softmax + edge_new + edge update + wsum (probs in-place, uint4 I/O)
__global__ void softmax_ednew(const float* __restrict__ exp_w, const float* __restrict__ exp_b,
                              const float* __restrict__ red_w, const float* __restrict__ red_b) {
    __shared__ float es[Nn];
    __shared__ float Ts[NHh][Nn];
    __shared__ float red3[24];
    int bn = blockIdx.x;
    int b = bn >> 10, n = bn & 1023;
    int tid = threadIdx.x;
    int w = tid >> 5, lane = tid & 31;
    __half* Ab = g_sattn + (((long)b * NHh + w) * Nn + n) * Nn;
    float* ep = g_edge + (long)b * Nn * Nn + (long)n * Nn;
    gdep();
    *(float4*)&es[tid * 4] = *(const float4*)&ep[tid * 4];
    __syncthreads();
    float ew = exp_w[w], eb = exp_b[w], rw = red_w[w];

    float4 r[8], e[8];
    #pragma unroll
    for (int k = 0; k < 4; k++) {
        uint4 u = *(const uint4*)&Ab[lane * 8 + k * 256];
        float2 fa = __half22float2(*(__half2*)&u.x);
        float2 fb2 = __half22float2(*(__half2*)&u.y);
        float2 fc = __half22float2(*(__half2*)&u.z);
        float2 fd = __half22float2(*(__half2*)&u.w);
        float4 ev0 = *(float4*)&es[lane * 8 + k * 256];
        float4 ev1 = *(float4*)&es[lane * 8 + k * 256 + 4];
        r[2 * k].x     = fa.x + ev0.x * ew + eb;
        r[2 * k].y     = fa.y + ev0.y * ew + eb;
        r[2 * k].z     = fb2.x + ev0.z * ew + eb;
        r[2 * k].w     = fb2.y + ev0.w * ew + eb;
        r[2 * k + 1].x = fc.x + ev1.x * ew + eb;
        r[2 * k + 1].y = fc.y + ev1.y * ew + eb;
        r[2 * k + 1].z = fd.x + ev1.z * ew + eb;
        r[2 * k + 1].w = fd.y + ev1.w * ew + eb;
    }
    float M = -INFINITY;
    #pragma unroll
    for (int k = 0; k < 8; k++)
        M = fmaxf(M, fmaxf(fmaxf(r[k].x, r[k].y), fmaxf(r[k].z, r[k].w)));
    #pragma unroll
    for (int o = 16; o > 0; o >>= 1) M = fmaxf(M, __shfl_xor_sync(0xffffffffu, M, o));
    float Z = 0.f;
    #pragma unroll
    for (int k = 0; k < 8; k++) {
        e[k].x = __expf(r[k].x - M); e[k].y = __expf(r[k].y - M);
        e[k].z = __expf(r[k].z - M); e[k].w = __expf(r[k].w - M);
        Z += e[k].x + e[k].y + e[k].z + e[k].w;
    }
    #pragma unroll
    for (int o = 16; o > 0; o >>= 1) Z += __shfl_xor_sync(0xffffffffu, Z, o);
    float inv = 1.f / Z;
    #pragma unroll
    for (int k = 0; k < 4; k++) {
        float4 a0, a1;
        a0.x = e[2 * k].x * inv;     a0.y = e[2 * k].y * inv;
        a0.z = e[2 * k].z * inv;     a0.w = e[2 * k].w * inv;
        a1.x = e[2 * k + 1].x * inv; a1.y = e[2 * k + 1].y * inv;
        a1.z = e[2 * k + 1].z * inv; a1.w = e[2 * k + 1].w * inv;
        uint4 u;
        __half2 p0 = __floats2half2_rn(a0.x, a0.y);
        __half2 p1 = __floats2half2_rn(a0.z, a0.w);
        __half2 p2 = __floats2half2_rn(a1.x, a1.y);
        __half2 p3 = __floats2half2_rn(a1.z, a1.w);
        u.x = *reinterpret_cast<unsigned*>(&p0);
        u.y = *reinterpret_cast<unsigned*>(&p1);
        u.z = *reinterpret_cast<unsigned*>(&p2);
        u.w = *reinterpret_cast<unsigned*>(&p3);
        *(uint4*)&Ab[lane * 8 + k * 256] = u;
        float4 t0, t1;
        t0.x = rw * (a0.x + r[2 * k].x); t0.y = rw * (a0.y + r[2 * k].y);
        t0.z = rw * (a0.z + r[2 * k].z); t0.w = rw * (a0.w + r[2 * k].w);
        t1.x = rw * (a1.x + r[2 * k + 1].x); t1.y = rw * (a1.y + r[2 * k + 1].y);
        t1.z = rw * (a1.z + r[2 * k + 1].z); t1.w = rw * (a1.w + r[2 * k + 1].w);
        *(float4*)&Ts[w][lane * 8 + k * 256]     = t0;
        *(float4*)&Ts[w][lane * 8 + k * 256 + 4] = t1;
    }
    __syncthreads();

    float rb = red_b[0];
    float4 en = {rb, rb, rb, rb};
    #pragma unroll
    for (int h = 0; h < NHh; h++) {
        float4 t = *(float4*)&Ts[h][tid * 4];
        en.x += t.x; en.y += t.y; en.z += t.z; en.w += t.w;
    }
    float4 ec = *(float4*)&es[tid * 4];
    ec.x += en.x; ec.y += en.y; ec.z += en.z; ec.w += en.w;
    *(float4*)&ep[tid * 4] = ec;
    float m2 = fmaxf(fmaxf(en.x, en.y), fmaxf(en.z, en.w));
    float f0 = __expf(en.x - m2), f1 = __expf(en.y - m2),
          f2 = __expf(en.z - m2), f3 = __expf(en.w - m2);
    float z2 = f0 + f1 + f2 + f3;
    float s2 = f0 * en.x + f1 * en.y + f2 * en.z + f3 * en.w;
    #pragma unroll
    for (int o = 16; o > 0; o >>= 1)
        mergeTriple(m2, z2, s2,
                    __shfl_xor_sync(0xffffffffu, m2, o),
                    __shfl_xor_sync(0xffffffffu, z2, o),
                    __shfl_xor_sync(0xffffffffu, s2, o));
    if (lane == 0) { red3[w * 3] = m2; red3[w * 3 + 1] = z2; red3[w * 3 + 2] = s2; }
    __syncthreads();
    if (tid < 32) {
        float mm = (lane < 8) ? red3[lane * 3]     : -INFINITY;
        float zz = (lane < 8) ? red3[lane * 3 + 1] : 0.f;
        float ss = (lane < 8) ? red3[lane * 3 + 2] : 0.f;
        #pragma unroll
        for (int o = 4; o > 0; o >>= 1)
            mergeTriple(mm, zz, ss,
                        __shfl_xor_sync(0xffffffffu, mm, o),
                        __shfl_xor_sync(0xffffffffu, zz, o),
                        __shfl_xor_sync(0xffffffffu, ss, o));
        if (lane == 0) g_wsum[bn] = ss / zz;
    }
}

// AV (fp16 WMMA): 32-row n-tiles (grid 512), 128 thr, cp.async 2-stage,
// in-block kk-split: warp w -> rows (w&1)*16, kk pair (w>>1).
#define AV32STG 10752
__global__ void av_half(void) {
    extern __shared__ char avsm[];
    int bh = blockIdx.y;
    int b = bh >> 3, h = bh & 7;
    int n0 = blockIdx.x * 32;
    int tid = threadIdx.x;  // 128
    int w = tid >> 5;
    int g = w & 1;
    int kg = w >> 1;
    const __half* Pb = g_sattn + (((long)b * NHh + h) * Nn + n0) * Nn;
    const __half* Vb = g_qkv_h + (long)b * Nn * 960 + 640 + h * DHh;
    unsigned smbase = (unsigned)__cvta_generic_to_shared(avsm);
    for (int s = 0; s < 2; s++) {
        __half* vp = (__half*)(avsm + s * AV32STG + 4608);
        for (int idx = tid; idx < 512; idx += 128) vp[(idx >> 3) * 48 + 40 + (idx & 7)] = __float2half(0.f);
    }
    wmma::fragment<wmma::accumulator, 16, 16, 16, float> c[3];
    #pragma unroll
    for (int j = 0; j < 3; j++) wmma::fill_fragment(c[j], 0.f);
    auto loadStage = [&](int m0, int s) {
        unsigned base = smbase + s * AV32STG;
        #pragma unroll
        for (int i = 0; i < 2; i++) {
            int idx = tid + i * 128, r = idx >> 3, c8 = (idx & 7) * 8;
            cpa16(base + r * 144 + c8 * 2, &Pb[(long)r * Nn + m0 + c8]);
        }
        #pragma unroll
        for (int i = 0; i < 3; i++) {
            int idx = tid + i * 128;
            if (idx < 320) {
                int r = idx / 5, c8 = (idx % 5) * 8;
                cpa16(base + 4608 + r * 96 + c8 * 2, &Vb[(long)(m0 + r) * 960 + c8]);
            }
        }
        CPA_COMMIT();
    };
    gdep();
    loadStage(0, 0);
    for (int k = 0; k < 16; k++) {
        if (k + 1 < 16) { loadStage((k + 1) * 64, (k + 1) & 1); CPA_WAIT1(); }
        else CPA_WAIT0();
        __syncthreads();
        __half (*Ps)[72] = (__half(*)[72])(avsm + (k & 1) * AV32STG);
        __half (*Vs)[48] = (__half(*)[48])(avsm + (k & 1) * AV32STG + 4608);
        #pragma unroll
        for (int kk2 = 0; kk2 < 2; kk2++) {
            int kk = kg * 2 + kk2;
            wmma::fragment<wmma::matrix_a, 16, 16, 16, __half, wmma::row_major> a;
            wmma::load_matrix_sync(a, &Ps[g * 16][kk * 16], 72);
            #pragma unroll
            for (int j = 0; j < 3; j++) {
                wmma::fragment<wmma::matrix_b, 16, 16, 16, __half, wmma::row_major> bf;
                wmma::load_matrix_sync(bf, &Vs[kk * 16][j * 16], 48);
                wmma::mma_sync(c[j], a, bf, c[j]);
            }
        }
        __syncthreads();
    }
    float* Cbase = (float*)avsm;
    #pragma unroll
    for (int j = 0; j < 3; j++)
        wmma::store_matrix_sync(Cbase + w * 768 + j * 16, c[j], 48, wmma::mem_row_major);
    __syncthreads();
    const float* wsp = g_wsum + b * Nn + n0;
    __half* op = g_nodeout_h + ((long)b * Nn + n0) * Cc + h * DHh;
    for (int idx = tid; idx < 320; idx += 128) {
        int r = idx / 10, c4 = (idx % 10) * 4;
        int g2 = r >> 4, r16 = r & 15;
        float4 v0 = *(float4*)&Cbase[g2 * 768 + r16 * 48 + c4];
        float4 v1 = *(float4*)&Cbase[(2 + g2) * 768 + r16 * 48 + c4];
        float wv = wsp[r];
        __half2 h0 = __floats2half2_rn(v0.x + v1.x + wv, v0.y + v1.y + wv);
        __half2 h1 = __floats2half2_rn(v0.z + v1.z + wv, v0.w + v1.w + wv);
        uint2 u;
        u.x = *reinterpret_cast<unsigned*>(&h0);
        u.y = *reinterpret_cast<unsigned*>(&h1);
        *reinterpret_cast<uint2*>(&op[(long)r * Cc + c4]) = u;
    }
}

static void* symv(const void* s) {
    void* p = nullptr;
    cudaGetSymbolAddress(&p, s);
    return p;
}

// PDL launch helper: ProgrammaticStreamSerialization on every launch
template <typename F, typename... Args>
static void pdl(dim3 grid, dim3 block, size_t smem, F f, Args... args) {
    cudaLaunchConfig_t cfg = {};
    cfg.gridDim = grid;
    cfg.blockDim = block;
    cfg.dynamicSmemBytes = smem;
    cfg.stream = 0;
    cudaLaunchAttribute at[1];
    at[0].id = cudaLaunchAttributeProgrammaticStreamSerialization;
    at[0].val.programmaticStreamSerializationAllowed = 1;
    cfg.attrs = at;
    cfg.numAttrs = 1;
    cudaLaunchKernelEx(&cfg, f, args...);
}

extern "C" void kernel_launch(void* const* d_in, const int* in_sizes, int n_in,
                              void* d_out, int out_size) {
    const float* x        = (const float*)d_in[0];
    const float* da_prior = (const float*)d_in[1];
    const float* qk_w     = (const float*)d_in[2];
    const float* fcp_w    = (const float*)d_in[3];
    const float* fcp_b    = (const float*)d_in[4];
    const float* ln1_g    = (const float*)d_in[5];
    const float* ln1_b    = (const float*)d_in[6];
    const float* gln_g    = (const float*)d_in[7];
    const float* gln_b    = (const float*)d_in[8];
    const float* qkv_w    = (const float*)d_in[9];
    const float* qkv_b    = (const float*)d_in[10];
    const float* proj_w   = (const float*)d_in[11];
    const float* proj_b   = (const float*)d_in[12];
    const float* exp_w    = (const float*)d_in[13];
    const float* exp_b    = (const float*)d_in[14];
    const float* red_w    = (const float*)d_in[15];
    const float* red_b    = (const float*)d_in[16];
    float* out = (float*)d_out;

    float*  p_node   = (float*)symv(g_node);
    float*  p_edge   = (float*)symv(g_edge);
    __half* p_node_h = (__half*)symv(g_node_h);
    __half* p_qk2_h  = (__half*)symv(g_qk2_h);
    __half* p_y_h    = (__half*)symv(g_y_h);
    __half* p_qkv_h  = (__half*)symv(g_qkv_h);
    __half* p_no_h   = (__half*)symv(g_nodeout_h);
    __half* p_qkw_h  = (__half*)symv(g_qkw_h);
    __half* p_qkvw_h = (__half*)symv(g_qkvw_h);
    __half* p_projw_h= (__half*)symv(g_projw_h);

    cudaFuncSetAttribute(gemm64, cudaFuncAttributeMaxDynamicSharedMemorySize, 2 * GSTG64);
    cudaFuncSetAttribute(av_half, cudaFuncAttributeMaxDynamicSharedMemorySize, 2 * AV32STG);

    pdl(dim3((N4_QK + N4_QKV + N4_PRJ + 255) / 256), dim3(256), 0, w2h_all,
        qk_w, qkv_w, proj_w);
    pdl(dim3(32, 10, Bb), dim3(256), 0, transpose_in, x);
    pdl(dim3(10, 32, 1), dim3(128), 2 * GSTG64, gemm64,
        (const __half*)p_node_h, (const __half*)p_qkw_h, (const float*)nullptr,
        (void*)p_qk2_h, Cc, Cc, Cc, 2 * Cc, 0L, 0L, 0L, 1.f, 1);
    pdl(dim3(16, 16, Bb), dim3(128), 2 * GSTG64, gemm64,
        (const __half*)p_qk2_h, (const __half*)(p_qk2_h + Cc), (const float*)nullptr,
        (void*)p_edge, Cc, 2 * Cc, 2 * Cc, Nn,
        (long)Nn * 2 * Cc, (long)Nn * 2 * Cc, (long)Nn * Nn, EDGE_SCALE, 0);
    pdl(dim3(258), dim3(256), 0, edgesm_fcp, da_prior, fcp_w, fcp_b);

    for (int l = 0; l < Ll; l++) {
        pdl(dim3(Bb * Nn / 8), dim3(256), 0, norm_kernel,
            ln1_g + l * Cc, ln1_b + l * Cc, gln_g + l * Cc, gln_b + l * Cc);
        pdl(dim3(15, 32, 1), dim3(128), 2 * GSTG64, gemm64,
            (const __half*)p_y_h, (const __half*)(p_qkvw_h + (long)l * 3 * Cc * Cc),
            (const float*)(qkv_b + l * 3 * Cc), (void*)p_qkv_h,
            Cc, Cc, Cc, 3 * Cc, 0L, 0L, 0L, 1.f, 1);
        pdl(dim3(8, 8, Bb * NHh), dim3(256), 0, attn_score_half);
        pdl(dim3(Bb * Nn), dim3(256), 0, softmax_ednew,
            exp_w + l * NHh, exp_b + l * NHh, red_w + l * NHh, red_b + l);
        pdl(dim3(32, Bb * NHh), dim3(128), 2 * AV32STG, av_half);
        pdl(dim3(5, 32, 1), dim3(128), 2 * GSTG64, gemm64,
            (const __half*)p_no_h, (const __half*)(p_projw_h + (long)l * Cc * Cc),
            (const float*)(proj_b + l * Cc), (void*)p_node,
            Cc, Cc, Cc, Cc, 0L, 0L, 0L, 1.f, 0);
    }
    pdl(dim3(32, 10, Bb), dim3(256), 0, transpose_out, out);
}